// round 12
// baseline (speedup 1.0000x reference)
#include <cuda_runtime.h>
#include <cuda_bf16.h>
#include <cuda_fp16.h>
#include <cstdint>

#define S    1024
#define CD   64
#define DD   256
#define FD   512
#define BNT  32
#define UK   96      // padded low-rank K (66 -> 96)

// bf16 split operands (bperm layout)
__device__ __align__(256) __nv_bfloat16 g_xth[BNT * S * CD];
__device__ __align__(256) __nv_bfloat16 g_xtl[BNT * S * CD];
__device__ __align__(256) __nv_bfloat16 g_uh [BNT * S * UK];
__device__ __align__(256) __nv_bfloat16 g_ul [BNT * S * UK];
__device__ __align__(256) __nv_bfloat16 g_wwh[BNT * S * 128];
__device__ __align__(256) __nv_bfloat16 g_wwl[BNT * S * 128];
__device__ __align__(256) __nv_bfloat16 g_gh [128 * UK];
__device__ __align__(256) __nv_bfloat16 g_gl [128 * UK];
__device__ __align__(256) __nv_bfloat16 g_ybh[BNT * S * DD];
__device__ __align__(256) __nv_bfloat16 g_ybl[BNT * S * DD];
__device__ __align__(256) __nv_bfloat16 g_wih[DD * CD];
__device__ __align__(256) __nv_bfloat16 g_wil[DD * CD];
__device__ __align__(256) __nv_bfloat16 g_woh[CD * DD];
__device__ __align__(256) __nv_bfloat16 g_wol[CD * DD];
// fp16 operands (bperm layout)
__device__ __align__(256) __half g_ph [(long)BNT * S * S];
__device__ __align__(256) __half g_tTh[BNT * S * DD];
__device__ __align__(256) __half g_hnh[BNT * S * DD];
__device__ __align__(256) __half g_hfh[BNT * S * FD];
__device__ __align__(256) __half g_w1h[FD * DD];
__device__ __align__(256) __half g_w2h[DD * FD];
// fp32
__device__ __align__(256) float g_t  [BNT * S * DD];
__device__ __align__(256) float g_xtf[BNT * S * CD];
__device__ __align__(256) float g_p  [(long)BNT * S * S];
__device__ __align__(256) float g_att[BNT * S * DD];

// ---------------------------------------------------------------------------
__device__ __forceinline__ int bperm(int k) {   // 16-bit k-perm within 32
    return (k & ~31) | (((k >> 1) & 3) << 3) | (((k >> 3) & 3) << 1) | (k & 1);
}

#define MMA_BF16(d, a0, a1, a2, a3, b0, b1)                                   \
    asm volatile("mma.sync.aligned.m16n8k16.row.col.f32.bf16.bf16.f32 "       \
                 "{%0,%1,%2,%3}, {%4,%5,%6,%7}, {%8,%9}, {%0,%1,%2,%3};\n"    \
                 : "+f"(d[0]), "+f"(d[1]), "+f"(d[2]), "+f"(d[3])             \
                 : "r"(a0), "r"(a1), "r"(a2), "r"(a3), "r"(b0), "r"(b1))

#define MMA_F16(d, a0, a1, a2, a3, b0, b1)                                    \
    asm volatile("mma.sync.aligned.m16n8k16.row.col.f32.f16.f16.f32 "         \
                 "{%0,%1,%2,%3}, {%4,%5,%6,%7}, {%8,%9}, {%0,%1,%2,%3};\n"    \
                 : "+f"(d[0]), "+f"(d[1]), "+f"(d[2]), "+f"(d[3])             \
                 : "r"(a0), "r"(a1), "r"(a2), "r"(a3), "r"(b0), "r"(b1))

#define UF(x) __float_as_uint(x)

#define CP16(dst, src)                                                        \
    asm volatile("cp.async.cg.shared.global [%0], [%1], 16;\n"                \
                 :: "r"(dst), "l"(src))

__device__ __forceinline__ int sw_addr(int m, int q) {
    return m * 16 + (((q ^ ((m >> 1) & 3)) & 3) << 2);
}

__device__ __forceinline__ void bf16split(float v, __nv_bfloat16& h, __nv_bfloat16& l) {
    h = __float2bfloat16_rn(v);
    l = __float2bfloat16_rn(v - __bfloat162float(h));
}

// ---------------------------------------------------------------------------
// cp.async MMA GEMM. MODE 0: fp16 single-pass, BK=64. MODE 1: bf16 2-split, BK=32.
// nk<=3: SINGLE-SHOT (all stages loaded upfront, one sync, zero mid-loop syncs).
// nk>3 : 3-stage pipeline (round-8 path).
// EPI 0: fp32 store  1: relu->fp16 bperm  2: +R->fp32  3: scatter to output
//     4: +R->bf16 split bperm  5: bf16 split bperm (no R)
// CAUSAL 1: tile skip (scores); 2: K limited to m0+128 (P@V)
// ---------------------------------------------------------------------------
template<int MODE, int EPI, int CAUSAL>
__global__ __launch_bounds__(256, 2)
void mma_gemm(const void* __restrict__ A, const void* __restrict__ Al_,
              long sAbn, int lda,
              const void* __restrict__ B, const void* __restrict__ Bl_,
              long sBbn, int ldb,
              void* __restrict__ Cv, void* __restrict__ C2v, long sCbn, int ldc,
              const float* __restrict__ R, long sRbn,
              float* __restrict__ Op, int K)
{
    const int bx = blockIdx.x, by = blockIdx.y, bz = blockIdx.z;
    if (CAUSAL == 1 && bx > 2 * by + 1) return;

    constexpr int SS = 6144;
    extern __shared__ __align__(16) float sh[];

    const int tid = threadIdx.x;
    const int w = tid >> 5, l = tid & 31;
    const int warp_m = (w & 3) * 32, warp_n = (w >> 2) * 32;
    const int g = l >> 2, cc = l & 3;
    const int m0 = by * 128, n0 = bx * 64;

    const char* Abp  = (const char*)A + (long)bz * sAbn * 2;
    const char* Bbp  = (const char*)B + (long)bz * sBbn * 2;
    const char* Ablp = (MODE == 1) ? ((const char*)Al_ + (long)bz * sAbn * 2) : nullptr;
    const char* Bblp = (MODE == 1) ? ((const char*)Bl_ + (long)bz * sBbn * 2) : nullptr;

    int Keff = K;
    if (CAUSAL == 2) { int lim = m0 + 128; if (lim < Keff) Keff = lim; }
    const int nk = (MODE == 0) ? (Keff >> 6) : (Keff >> 5);

    const int am = tid >> 2, aj = tid & 3;
    const long oA0 = ((long)(m0 + am)      * lda + (long)aj * 8) * 2;
    const long oA1 = ((long)(m0 + am + 64) * lda + (long)aj * 8) * 2;
    const long oB  = ((long)(n0 + am)      * ldb + (long)aj * 8) * 2;
    const int swz  = ((aj ^ ((am >> 1) & 3)) & 3) << 2;
    const int slA0 = am * 16 + swz;
    const int slA1 = (am + 64) * 16 + swz;
    const int slB  = 2048 + am * 16 + swz;
    const uint32_t sbb = (uint32_t)__cvta_generic_to_shared(sh);

    auto issue = [&](int st, int kt) {
        uint32_t s0 = sbb + (uint32_t)(st * SS) * 4u;
        if (MODE == 0) {
            long kb = (long)kt * 128;
            CP16(s0 + slA0 * 4, Abp + oA0 + kb);
            CP16(s0 + slA1 * 4, Abp + oA1 + kb);
            CP16(s0 + slB  * 4, Bbp + oB  + kb);
            CP16(s0 + (slA0 + 3072) * 4, Abp + oA0 + kb + 64);
            CP16(s0 + (slA1 + 3072) * 4, Abp + oA1 + kb + 64);
            CP16(s0 + (slB  + 3072) * 4, Bbp + oB  + kb + 64);
        } else {
            long kb = (long)kt * 64;
            CP16(s0 + slA0 * 4, Abp + oA0 + kb);
            CP16(s0 + slA1 * 4, Abp + oA1 + kb);
            CP16(s0 + slB  * 4, Bbp + oB  + kb);
            CP16(s0 + (slA0 + 3072) * 4, Ablp + oA0 + kb);
            CP16(s0 + (slA1 + 3072) * 4, Ablp + oA1 + kb);
            CP16(s0 + (slB  + 3072) * 4, Bblp + oB  + kb);
        }
        asm volatile("cp.async.commit_group;\n" ::);
    };

    float acc[2][4][4] = {};

    auto compute_stage = [&](int st) {
        const float* s0A = sh + st * SS;
        const float* s0B = s0A + 2048;
        const float* s1A = s0A + 3072;
        const float* s1B = s0A + 5120;

        float4 Ah[2][2], Bh[4], Al[2][2], Bl[4];
        #pragma unroll
        for (int mi = 0; mi < 2; mi++) {
            int mr = warp_m + mi * 16 + g;
            Ah[mi][0] = *(const float4*)&s0A[sw_addr(mr, cc)];
            Ah[mi][1] = *(const float4*)&s0A[sw_addr(mr + 8, cc)];
            Al[mi][0] = *(const float4*)&s1A[sw_addr(mr, cc)];
            Al[mi][1] = *(const float4*)&s1A[sw_addr(mr + 8, cc)];
        }
        #pragma unroll
        for (int nj = 0; nj < 4; nj++) {
            int nr = warp_n + nj * 8 + g;
            Bh[nj] = *(const float4*)&s0B[sw_addr(nr, cc)];
            Bl[nj] = *(const float4*)&s1B[sw_addr(nr, cc)];
        }

        #pragma unroll
        for (int mi = 0; mi < 2; mi++) {
            #pragma unroll
            for (int nj = 0; nj < 4; nj++) {
                float* d = acc[mi][nj];
                if (MODE == 0) {
                    MMA_F16(d, UF(Ah[mi][0].x), UF(Ah[mi][1].x), UF(Ah[mi][0].y), UF(Ah[mi][1].y),
                               UF(Bh[nj].x), UF(Bh[nj].y));
                    MMA_F16(d, UF(Ah[mi][0].z), UF(Ah[mi][1].z), UF(Ah[mi][0].w), UF(Ah[mi][1].w),
                               UF(Bh[nj].z), UF(Bh[nj].w));
                    MMA_F16(d, UF(Al[mi][0].x), UF(Al[mi][1].x), UF(Al[mi][0].y), UF(Al[mi][1].y),
                               UF(Bl[nj].x), UF(Bl[nj].y));
                    MMA_F16(d, UF(Al[mi][0].z), UF(Al[mi][1].z), UF(Al[mi][0].w), UF(Al[mi][1].w),
                               UF(Bl[nj].z), UF(Bl[nj].w));
                } else {
                    MMA_BF16(d, UF(Ah[mi][0].x), UF(Ah[mi][1].x), UF(Ah[mi][0].y), UF(Ah[mi][1].y),
                                UF(Bh[nj].x), UF(Bh[nj].y));
                    MMA_BF16(d, UF(Ah[mi][0].x), UF(Ah[mi][1].x), UF(Ah[mi][0].y), UF(Ah[mi][1].y),
                                UF(Bl[nj].x), UF(Bl[nj].y));
                    MMA_BF16(d, UF(Al[mi][0].x), UF(Al[mi][1].x), UF(Al[mi][0].y), UF(Al[mi][1].y),
                                UF(Bh[nj].x), UF(Bh[nj].y));
                    MMA_BF16(d, UF(Ah[mi][0].z), UF(Ah[mi][1].z), UF(Ah[mi][0].w), UF(Ah[mi][1].w),
                                UF(Bh[nj].z), UF(Bh[nj].w));
                    MMA_BF16(d, UF(Ah[mi][0].z), UF(Ah[mi][1].z), UF(Ah[mi][0].w), UF(Ah[mi][1].w),
                                UF(Bl[nj].z), UF(Bl[nj].w));
                    MMA_BF16(d, UF(Al[mi][0].z), UF(Al[mi][1].z), UF(Al[mi][0].w), UF(Al[mi][1].w),
                                UF(Bh[nj].z), UF(Bh[nj].w));
                }
            }
        }
    };

    if (nk <= 3) {
        // ---- single-shot: everything resident, one sync, no mid-loop waits ----
        for (int i = 0; i < nk; i++) issue(i, i);
        asm volatile("cp.async.wait_group 0;\n" ::);
        __syncthreads();
        for (int kt = 0; kt < nk; kt++) compute_stage(kt);
    } else {
        issue(0, 0);
        issue(1, 1);
        for (int kt = 0; kt < nk; kt++) {
            asm volatile("cp.async.wait_group 1;\n" ::);
            __syncthreads();
            if (kt + 2 < nk) issue((kt + 2) % 3, kt + 2);
            else             asm volatile("cp.async.commit_group;\n" ::);
            compute_stage(kt % 3);
        }
    }

    // ---- epilogue ----
    if (EPI == 3) {
        const int b = bz >> 3, n = bz & 7;
        #pragma unroll
        for (int mi = 0; mi < 2; mi++) {
            #pragma unroll
            for (int nj = 0; nj < 4; nj++) {
                int row = m0 + warp_m + mi * 16 + g;
                int col = n0 + warp_n + nj * 8 + 2 * cc;
                Op[((long)(b * 64 + col)     * 8 + n) * 1024 + row]     = acc[mi][nj][0];
                Op[((long)(b * 64 + col + 1) * 8 + n) * 1024 + row]     = acc[mi][nj][1];
                Op[((long)(b * 64 + col)     * 8 + n) * 1024 + row + 8] = acc[mi][nj][2];
                Op[((long)(b * 64 + col + 1) * 8 + n) * 1024 + row + 8] = acc[mi][nj][3];
            }
        }
    } else if (EPI == 1) {
        __half* Cb = (__half*)Cv + (long)bz * sCbn;
        #pragma unroll
        for (int mi = 0; mi < 2; mi++) {
            #pragma unroll
            for (int nj = 0; nj < 4; nj++) {
                int row = m0 + warp_m + mi * 16 + g;
                int col = n0 + warp_n + nj * 8 + 2 * cc;
                int p0 = bperm(col);
                *(__half2*)&Cb[(long)row * ldc + p0] =
                    __floats2half2_rn(fmaxf(acc[mi][nj][0], 0.f), fmaxf(acc[mi][nj][1], 0.f));
                *(__half2*)&Cb[(long)(row + 8) * ldc + p0] =
                    __floats2half2_rn(fmaxf(acc[mi][nj][2], 0.f), fmaxf(acc[mi][nj][3], 0.f));
            }
        }
    } else if (EPI == 4 || EPI == 5) {
        __nv_bfloat16* Cb  = (__nv_bfloat16*)Cv  + (long)bz * sCbn;
        __nv_bfloat16* C2b = (__nv_bfloat16*)C2v + (long)bz * sCbn;
        const float* Rb = (EPI == 4) ? (R + (long)bz * sRbn) : nullptr;
        #pragma unroll
        for (int mi = 0; mi < 2; mi++) {
            #pragma unroll
            for (int nj = 0; nj < 4; nj++) {
                int row = m0 + warp_m + mi * 16 + g;
                int col = n0 + warp_n + nj * 8 + 2 * cc;
                int p0 = bperm(col);
                float v[4] = {acc[mi][nj][0], acc[mi][nj][1], acc[mi][nj][2], acc[mi][nj][3]};
                if (EPI == 4) {
                    float2 r0 = *(const float2*)(Rb + (long)row * ldc + col);
                    float2 r1 = *(const float2*)(Rb + (long)(row + 8) * ldc + col);
                    v[0] += r0.x; v[1] += r0.y; v[2] += r1.x; v[3] += r1.y;
                }
                __nv_bfloat16 h[4], lo[4];
                #pragma unroll
                for (int q = 0; q < 4; q++) bf16split(v[q], h[q], lo[q]);
                *(__nv_bfloat162*)&Cb [(long)row * ldc + p0]       = __nv_bfloat162(h[0],  h[1]);
                *(__nv_bfloat162*)&Cb [(long)(row + 8) * ldc + p0] = __nv_bfloat162(h[2],  h[3]);
                *(__nv_bfloat162*)&C2b[(long)row * ldc + p0]       = __nv_bfloat162(lo[0], lo[1]);
                *(__nv_bfloat162*)&C2b[(long)(row + 8) * ldc + p0] = __nv_bfloat162(lo[2], lo[3]);
            }
        }
    } else {
        float* Cb = (float*)Cv + (long)bz * sCbn;
        const float* Rb = (EPI == 2) ? (R + (long)bz * sRbn) : nullptr;
        #pragma unroll
        for (int mi = 0; mi < 2; mi++) {
            #pragma unroll
            for (int nj = 0; nj < 4; nj++) {
                int row = m0 + warp_m + mi * 16 + g;
                int col = n0 + warp_n + nj * 8 + 2 * cc;
                float v[4] = {acc[mi][nj][0], acc[mi][nj][1], acc[mi][nj][2], acc[mi][nj][3]};
                if (EPI == 2) {
                    float2 r0 = *(const float2*)(Rb + (long)row * ldc + col);
                    float2 r1 = *(const float2*)(Rb + (long)(row + 8) * ldc + col);
                    v[0] += r0.x; v[1] += r0.y; v[2] += r1.x; v[3] += r1.y;
                }
                *(float2*)(Cb + (long)row * ldc + col)       = make_float2(v[0], v[1]);
                *(float2*)(Cb + (long)(row + 8) * ldc + col) = make_float2(v[2], v[3]);
            }
        }
    }
}

// ---------------------------------------------------------------------------
__global__ __launch_bounds__(256)
void wprep_k(const float* __restrict__ W_in, const float* __restrict__ W_out,
             const float* __restrict__ W1, const float* __restrict__ W2,
             __nv_bfloat16* __restrict__ wih, __nv_bfloat16* __restrict__ wil,
             __nv_bfloat16* __restrict__ woh, __nv_bfloat16* __restrict__ wol,
             __half* __restrict__ w1h, __half* __restrict__ w2h)
{
    int i = blockIdx.x * 256 + threadIdx.x;
    const int nWi = DD * CD, nWo = CD * DD, nW1 = FD * DD;
    if (i < nWi) {
        int row = i / CD, k = i % CD;
        int o = row * CD + bperm(k);
        bf16split(W_in[i], wih[o], wil[o]);
    } else if (i < nWi + nWo) {
        int j = i - nWi;
        int row = j / DD, k = j % DD;
        int o = row * DD + bperm(k);
        bf16split(W_out[j], woh[o], wol[o]);
    } else if (i < nWi + nWo + nW1) {
        int j = i - nWi - nWo;
        int row = j / DD, k = j % DD;
        w1h[row * DD + bperm(k)] = __float2half_rn(W1[j]);
    } else {
        int j = i - nWi - nWo - nW1;
        if (j < DD * FD) {
            int row = j / FD, k = j % FD;
            w2h[row * FD + bperm(k)] = __float2half_rn(W2[j]);
        }
    }
}

// G = V^T V (smem-cached). V[c,j<64]=g_c*W_in[c,j], V[c,64]=-g_c, V[c,65]=b_c.
__global__ __launch_bounds__(256)
void gprep_k(const float* __restrict__ W_in, const float* __restrict__ g1,
             const float* __restrict__ b1,
             __nv_bfloat16* __restrict__ gh, __nv_bfloat16* __restrict__ gl)
{
    extern __shared__ float sV[];
    const int tid = threadIdx.x;
    for (int idx = tid; idx < DD * UK; idx += 256) {
        int c = idx / UK, j = idx % UK;
        float gc = g1[c];
        float v = (j < 64) ? gc * W_in[c * CD + j] : ((j == 64) ? -gc : ((j == 65) ? b1[c] : 0.f));
        sV[idx] = v;
    }
    __syncthreads();
    int oidx = blockIdx.x * 256 + tid;
    if (oidx >= 128 * UK) return;
    int n = oidx / UK, k = oidx % UK;
    float val = 0.f;
    if (n < 66 && k < 66) {
        #pragma unroll 4
        for (int c = 0; c < DD; c++)
            val += sV[c * UK + n] * sV[c * UK + k];
    }
    __nv_bfloat16 h, lo;
    bf16split(val, h, lo);
    int o = n * UK + bperm(k);
    gh[o] = h; gl[o] = lo;
}

__global__ __launch_bounds__(256)
void transpose_x_k(const float* __restrict__ x, __nv_bfloat16* __restrict__ xth,
                   __nv_bfloat16* __restrict__ xtl, float* __restrict__ xtf)
{
    __shared__ float tile[32][33];
    int tx = threadIdx.x & 31, ty = threadIdx.x >> 5;
    int bn = blockIdx.z, b = bn >> 3, n = bn & 7;
    int s0 = blockIdx.x * 32, c0 = blockIdx.y * 32;
    const float* src = x + ((long)b * 64 * 8 + n) * 1024;
    #pragma unroll
    for (int i = 0; i < 4; i++)
        tile[ty + 8 * i][tx] = src[(long)(c0 + ty + 8 * i) * 8192 + s0 + tx];
    __syncthreads();
    __nv_bfloat16* dh = xth + (long)bn * (S * CD);
    __nv_bfloat16* dl = xtl + (long)bn * (S * CD);
    float* df = xtf + (long)bn * (S * CD);
    int pc = bperm(c0 + tx);
    #pragma unroll
    for (int i = 0; i < 4; i++) {
        float v = tile[tx][ty + 8 * i];
        long row = (long)(s0 + ty + 8 * i);
        bf16split(v, dh[row * 64 + pc], dl[row * 64 + pc]);
        df[row * 64 + c0 + tx] = v;
    }
}

// LN1 stats + build U (one warp per row)
__global__ __launch_bounds__(256)
void stats_ubuild_k(const float* __restrict__ t, const float* __restrict__ xtf,
                    __nv_bfloat16* __restrict__ uh, __nv_bfloat16* __restrict__ ul)
{
    int warp = (blockIdx.x * blockDim.x + threadIdx.x) >> 5;
    int lane = threadIdx.x & 31;
    const float* x = t + (long)warp * DD;

    float s = 0.f, ss = 0.f;
    #pragma unroll
    for (int i = 0; i < 8; i++) {
        float v = x[lane + 32 * i];
        s += v; ss += v * v;
    }
    #pragma unroll
    for (int o = 16; o; o >>= 1) {
        s  += __shfl_xor_sync(0xffffffffu, s,  o);
        ss += __shfl_xor_sync(0xffffffffu, ss, o);
    }
    float mu = s * (1.f / DD);
    float var = ss * (1.f / DD) - mu * mu;
    float rs = rsqrtf(var + 1e-5f);

    const float* xr = xtf + (long)warp * CD;
    __nv_bfloat16* oh = uh + (long)warp * UK;
    __nv_bfloat16* ol = ul + (long)warp * UK;
    #pragma unroll
    for (int i = 0; i < 3; i++) {
        int j = lane + 32 * i;
        float v;
        if (j < 64)       v = rs * xr[j];
        else if (j == 64) v = rs * mu;
        else if (j == 65) v = 1.f;
        else              v = 0.f;
        __nv_bfloat16 h, lo;
        bf16split(v, h, lo);
        oh[bperm(j)] = h; ol[bperm(j)] = lo;
    }
}

// t -> tT fp16 [d][s], bperm on s
__global__ __launch_bounds__(256)
void transpose_t_k(const float* __restrict__ t, __half* __restrict__ tT)
{
    __shared__ float tile[32][33];
    int tx = threadIdx.x & 31, ty = threadIdx.x >> 5;
    int bn = blockIdx.z;
    int s0 = blockIdx.x * 32, d0 = blockIdx.y * 32;
    const float* src = t + (long)bn * (S * DD);
    #pragma unroll
    for (int i = 0; i < 4; i++)
        tile[ty + 8 * i][tx] = src[(long)(s0 + ty + 8 * i) * 256 + d0 + tx];
    __syncthreads();
    __half* dst = tT + (long)bn * (S * DD);
    int ps = bperm(s0 + tx);
    #pragma unroll
    for (int i = 0; i < 4; i++)
        dst[(long)(d0 + ty + 8 * i) * 1024 + ps] = __float2half_rn(tile[tx][ty + 8 * i]);
}

// LN2 -> fp16 (bperm)
__global__ __launch_bounds__(256)
void ln_half_k(const float* __restrict__ in, __half* __restrict__ out,
               const float* __restrict__ gam, const float* __restrict__ bet)
{
    int warp = (blockIdx.x * blockDim.x + threadIdx.x) >> 5;
    int lane = threadIdx.x & 31;
    const float* x = in + (long)warp * DD;

    float v[8], s = 0.f, ss = 0.f;
    #pragma unroll
    for (int i = 0; i < 8; i++) {
        v[i] = x[lane + 32 * i];
        s += v[i]; ss += v[i] * v[i];
    }
    #pragma unroll
    for (int o = 16; o; o >>= 1) {
        s  += __shfl_xor_sync(0xffffffffu, s,  o);
        ss += __shfl_xor_sync(0xffffffffu, ss, o);
    }
    float mu = s * (1.f / DD);
    float var = ss * (1.f / DD) - mu * mu;
    float rs = rsqrtf(var + 1e-5f);

    __half* o_ = out + (long)warp * DD;
    #pragma unroll
    for (int i = 0; i < 8; i++) {
        int c = lane + 32 * i;
        o_[bperm(c)] = __float2half_rn((v[i] - mu) * rs * gam[c] + bet[c]);
    }
}

// ---------------------------------------------------------------------------
// softmax, 3-pass chunked: reads only cols < kend (causal bound).
// pass1 max, pass2 sum of __expf (L1-hot re-read), pass3 normalized fp16 write.
// ---------------------------------------------------------------------------
__global__ __launch_bounds__(256)
void softmax_k(const float* __restrict__ p, __half* __restrict__ ph)
{
    int warp = (blockIdx.x * blockDim.x + threadIdx.x) >> 5;
    int lane = threadIdx.x & 31;
    int q = warp & (S - 1);
    const float* row = p + (long)warp * S;
    __half* rowh = ph + (long)warp * S;

    const int kend = ((q >> 7) + 1) << 7;   // 128-multiple covering causal range

    float mx = -3.4e38f;
    for (int c0 = 0; c0 < kend; c0 += 128) {
        #pragma unroll
        for (int i = 0; i < 4; i++) {
            int col = c0 + lane + 32 * i;
            float v = (col <= q) ? row[col] : -3.4e38f;
            mx = fmaxf(mx, v);
        }
    }
    #pragma unroll
    for (int o = 16; o; o >>= 1) mx = fmaxf(mx, __shfl_xor_sync(0xffffffffu, mx, o));

    float sum = 0.f;
    for (int c0 = 0; c0 < kend; c0 += 128) {
        #pragma unroll
        for (int i = 0; i < 4; i++) {
            int col = c0 + lane + 32 * i;
            if (col <= q) sum += __expf(row[col] - mx);
        }
    }
    #pragma unroll
    for (int o = 16; o; o >>= 1) sum += __shfl_xor_sync(0xffffffffu, sum, o);
    float inv = 1.f / sum;

    for (int c0 = 0; c0 < kend; c0 += 128) {
        #pragma unroll
        for (int i = 0; i < 4; i++) {
            int col = c0 + lane + 32 * i;
            float v = (col <= q) ? __expf(row[col] - mx) * inv : 0.f;
            rowh[bperm(col)] = __float2half_rn(v);
        }
    }
}

// ---------------------------------------------------------------------------
extern "C" void kernel_launch(void* const* d_in, const int* in_sizes, int n_in,
                              void* d_out, int out_size)
{
    (void)in_sizes; (void)n_in; (void)out_size;
    const float* buffer = (const float*)d_in[0];
    const float* W_in   = (const float*)d_in[1];
    const float* ln1_g  = (const float*)d_in[2];
    const float* ln1_b  = (const float*)d_in[3];
    const float* ln2_g  = (const float*)d_in[4];
    const float* ln2_b  = (const float*)d_in[5];
    const float* W1     = (const float*)d_in[6];
    const float* W2     = (const float*)d_in[7];
    const float* W_out  = (const float*)d_in[8];
    float* out = (float*)d_out;

    __nv_bfloat16 *xth, *xtl, *uh, *ul, *wwh, *wwl, *gh, *gl, *ybh, *ybl;
    __nv_bfloat16 *wih, *wil, *woh, *wol;
    __half *ph, *tTh, *hnh, *hfh, *w1h, *w2h;
    float *t, *xtf, *p, *att;
    cudaGetSymbolAddress((void**)&xth, g_xth);
    cudaGetSymbolAddress((void**)&xtl, g_xtl);
    cudaGetSymbolAddress((void**)&uh,  g_uh);
    cudaGetSymbolAddress((void**)&ul,  g_ul);
    cudaGetSymbolAddress((void**)&wwh, g_wwh);
    cudaGetSymbolAddress((void**)&wwl, g_wwl);
    cudaGetSymbolAddress((void**)&gh,  g_gh);
    cudaGetSymbolAddress((void**)&gl,  g_gl);
    cudaGetSymbolAddress((void**)&ybh, g_ybh);
    cudaGetSymbolAddress((void**)&ybl, g_ybl);
    cudaGetSymbolAddress((void**)&wih, g_wih);
    cudaGetSymbolAddress((void**)&wil, g_wil);
    cudaGetSymbolAddress((void**)&woh, g_woh);
    cudaGetSymbolAddress((void**)&wol, g_wol);
    cudaGetSymbolAddress((void**)&ph,  g_ph);
    cudaGetSymbolAddress((void**)&tTh, g_tTh);
    cudaGetSymbolAddress((void**)&hnh, g_hnh);
    cudaGetSymbolAddress((void**)&hfh, g_hfh);
    cudaGetSymbolAddress((void**)&w1h, g_w1h);
    cudaGetSymbolAddress((void**)&w2h, g_w2h);
    cudaGetSymbolAddress((void**)&t,   g_t);
    cudaGetSymbolAddress((void**)&xtf, g_xtf);
    cudaGetSymbolAddress((void**)&p,   g_p);
    cudaGetSymbolAddress((void**)&att, g_att);

    const long sT = (long)S * DD;
    const long sP = (long)S * S;
    const long sH = (long)S * FD;
    const long sX = (long)S * CD;
    const long sU = (long)S * UK;
    const long sWL = (long)S * 128;

    const int smem_b = 3 * 6144 * 4;
    const int smem_g = DD * UK * 4;
    cudaFuncSetAttribute(mma_gemm<1, 0, 0>, cudaFuncAttributeMaxDynamicSharedMemorySize, smem_b);
    cudaFuncSetAttribute(mma_gemm<1, 5, 0>, cudaFuncAttributeMaxDynamicSharedMemorySize, smem_b);
    cudaFuncSetAttribute(mma_gemm<1, 0, 1>, cudaFuncAttributeMaxDynamicSharedMemorySize, smem_b);
    cudaFuncSetAttribute(mma_gemm<0, 2, 2>, cudaFuncAttributeMaxDynamicSharedMemorySize, smem_b);
    cudaFuncSetAttribute(mma_gemm<0, 1, 0>, cudaFuncAttributeMaxDynamicSharedMemorySize, smem_b);
    cudaFuncSetAttribute(mma_gemm<0, 4, 0>, cudaFuncAttributeMaxDynamicSharedMemorySize, smem_b);
    cudaFuncSetAttribute(mma_gemm<1, 3, 0>, cudaFuncAttributeMaxDynamicSharedMemorySize, smem_b);
    cudaFuncSetAttribute(gprep_k, cudaFuncAttributeMaxDynamicSharedMemorySize, smem_g);

    // prep
    {
        const int ntot = DD * CD + CD * DD + FD * DD + DD * FD;
        wprep_k<<<(ntot + 255) / 256, 256>>>(W_in, W_out, W1, W2,
                                             wih, wil, woh, wol, w1h, w2h);
    }
    gprep_k<<<(128 * UK + 255) / 256, 256, smem_g>>>(W_in, ln1_g, ln1_b, gh, gl);

    // 0) transpose x -> xt bf16 split + xtf fp32
    transpose_x_k<<<dim3(32, 2, BNT), 256>>>(buffer, xth, xtl, xtf);

    // 1) t = xt . W_in^T   (bf16 2-split, single-shot nk=2)
    mma_gemm<1, 0, 0><<<dim3(4, 8, BNT), 256, smem_b>>>(
        xth, xtl, sX, CD,  wih, wil, 0, CD,
        t, nullptr, sT, DD,  nullptr, 0, nullptr, CD);

    // 2) LN1 stats + build U
    stats_ubuild_k<<<(BNT * S) / 8, 256>>>(t, xtf, uh, ul);

    // 3) W = U . G  (bf16 2-split, K=96, single-shot nk=3)
    mma_gemm<1, 5, 0><<<dim3(2, 8, BNT), 256, smem_b>>>(
        uh, ul, sU, UK,  gh, gl, 0, UK,
        wwh, wwl, sWL, 128,  nullptr, 0, nullptr, UK);

    // 4) scores = W . U^T  (bf16 2-split, K=96, single-shot, causal tile skip)
    mma_gemm<1, 0, 1><<<dim3(16, 8, BNT), 256, smem_b>>>(
        wwh, wwl, sWL, 128,  uh, ul, sU, UK,
        p, nullptr, sP, S,  nullptr, 0, nullptr, UK);

    // 5) softmax -> fp16 p (bperm)
    softmax_k<<<(BNT * S) / 8, 256>>>(p, ph);

    // 6) transpose t -> tT fp16 (bperm s)
    transpose_t_k<<<dim3(32, 8, BNT), 256>>>(t, tTh);

    // 7) att = p . t + t   (fp16 single, BK64, K limited)
    mma_gemm<0, 2, 2><<<dim3(4, 8, BNT), 256, smem_b>>>(
        ph, nullptr, sP, S,  tTh, nullptr, sT, S,
        att, nullptr, sT, DD,  t, sT, nullptr, S);

    // 8) hn = LN2(att) -> fp16 (bperm)
    ln_half_k<<<(BNT * S) / 8, 256>>>(att, hnh, ln2_g, ln2_b);

    // 9) hf = relu(hn . W1^T)  (fp16)
    mma_gemm<0, 1, 0><<<dim3(8, 8, BNT), 256, smem_b>>>(
        hnh, nullptr, sT, DD,  w1h, nullptr, 0, DD,
        hfh, nullptr, sH, FD,  nullptr, 0, nullptr, DD);

    // 10) y = hf . W2^T + t -> bf16 hi/lo (bperm)
    mma_gemm<0, 4, 0><<<dim3(4, 8, BNT), 256, smem_b>>>(
        hfh, nullptr, sH, FD,  w2h, nullptr, 0, FD,
        ybh, ybl, sT, DD,  t, sT, nullptr, FD);

    // 11) out = y . W_out^T (bf16 2-split, scatter epilogue)
    mma_gemm<1, 3, 0><<<dim3(1, 8, BNT), 256, smem_b>>>(
        ybh, ybl, sT, DD,  woh, wol, 0, DD,
        nullptr, nullptr, 0, 0,  nullptr, 0, out, DD);
}

// round 13
// speedup vs baseline: 1.0410x; 1.0410x over previous
#include <cuda_runtime.h>
#include <cuda_bf16.h>
#include <cuda_fp16.h>
#include <cstdint>

#define S    1024
#define CD   64
#define DD   256
#define FD   512
#define BNT  32
#define UK   96

// bf16 split operands (bperm layout)
__device__ __align__(256) __nv_bfloat16 g_xth[BNT * S * CD];
__device__ __align__(256) __nv_bfloat16 g_xtl[BNT * S * CD];
__device__ __align__(256) __nv_bfloat16 g_uh [BNT * S * UK];
__device__ __align__(256) __nv_bfloat16 g_ul [BNT * S * UK];
__device__ __align__(256) __nv_bfloat16 g_wwh[BNT * S * 128];
__device__ __align__(256) __nv_bfloat16 g_wwl[BNT * S * 128];
__device__ __align__(256) __nv_bfloat16 g_gh [128 * UK];
__device__ __align__(256) __nv_bfloat16 g_gl [128 * UK];
__device__ __align__(256) __nv_bfloat16 g_ybh[BNT * S * DD];
__device__ __align__(256) __nv_bfloat16 g_ybl[BNT * S * DD];
__device__ __align__(256) __nv_bfloat16 g_wih[DD * CD];
__device__ __align__(256) __nv_bfloat16 g_wil[DD * CD];
__device__ __align__(256) __nv_bfloat16 g_woh[CD * DD];
__device__ __align__(256) __nv_bfloat16 g_wol[CD * DD];
// fp16 operands (bperm layout)
__device__ __align__(256) __half g_tTh[BNT * S * DD];
__device__ __align__(256) __half g_hnh[BNT * S * DD];
__device__ __align__(256) __half g_hfh[BNT * S * FD];
__device__ __align__(256) __half g_w1h[FD * DD];
__device__ __align__(256) __half g_w2h[DD * FD];
// fp32
__device__ __align__(256) float g_t  [BNT * S * DD];
__device__ __align__(256) float g_xtf[BNT * S * CD];
__device__ __align__(256) float g_att[BNT * S * DD];

// ---------------------------------------------------------------------------
__device__ __forceinline__ int bperm(int k) {
    return (k & ~31) | (((k >> 1) & 3) << 3) | (((k >> 3) & 3) << 1) | (k & 1);
}

#define MMA_BF16(d, a0, a1, a2, a3, b0, b1)                                   \
    asm volatile("mma.sync.aligned.m16n8k16.row.col.f32.bf16.bf16.f32 "       \
                 "{%0,%1,%2,%3}, {%4,%5,%6,%7}, {%8,%9}, {%0,%1,%2,%3};\n"    \
                 : "+f"(d[0]), "+f"(d[1]), "+f"(d[2]), "+f"(d[3])             \
                 : "r"(a0), "r"(a1), "r"(a2), "r"(a3), "r"(b0), "r"(b1))

#define MMA_F16(d, a0, a1, a2, a3, b0, b1)                                    \
    asm volatile("mma.sync.aligned.m16n8k16.row.col.f32.f16.f16.f32 "         \
                 "{%0,%1,%2,%3}, {%4,%5,%6,%7}, {%8,%9}, {%0,%1,%2,%3};\n"    \
                 : "+f"(d[0]), "+f"(d[1]), "+f"(d[2]), "+f"(d[3])             \
                 : "r"(a0), "r"(a1), "r"(a2), "r"(a3), "r"(b0), "r"(b1))

#define UF(x) __float_as_uint(x)

#define CP16(dst, src)                                                        \
    asm volatile("cp.async.cg.shared.global [%0], [%1], 16;\n"                \
                 :: "r"(dst), "l"(src))

__device__ __forceinline__ int sw_addr(int m, int q) {
    return m * 16 + (((q ^ ((m >> 1) & 3)) & 3) << 2);
}

__device__ __forceinline__ void bf16split(float v, __nv_bfloat16& h, __nv_bfloat16& l) {
    h = __float2bfloat16_rn(v);
    l = __float2bfloat16_rn(v - __bfloat162float(h));
}

// ---------------------------------------------------------------------------
// Fused flash attention: scores (W.U^T, K=96 bf16-split) -> online softmax ->
// p.tT (fp16) -> att = p.t/l + t.  One CTA = 64 q-rows x 256 out cols.
// smem words: W hi 0 / lo 3072, U hi 6144 / lo 9216, tT 12288 (8192),
//             p 20480 (2048), red 22528..22848
// ---------------------------------------------------------------------------
__global__ __launch_bounds__(256)
void fa_k(const __nv_bfloat16* __restrict__ wwh, const __nv_bfloat16* __restrict__ wwl,
          const __nv_bfloat16* __restrict__ uh,  const __nv_bfloat16* __restrict__ ul,
          const __half* __restrict__ tTh,
          const float* __restrict__ t, float* __restrict__ att)
{
    extern __shared__ __align__(16) float sm[];
    const int bz = blockIdx.z;
    const int qt = 15 - blockIdx.x;          // big tiles first
    const int m0 = qt * 64;
    const int tid = threadIdx.x;
    const int w = tid >> 5, l = tid & 31;
    const int g = l >> 2, cc = l & 3;
    const int warp_m = (w & 3) * 16;         // score/out row block (16 rows)
    const int warp_n = (w >> 2) * 32;        // score col block (32 cols)
    const int warp_no = (w >> 2) * 128;      // out col block (128 cols)

    const __nv_bfloat16* Wh = wwh + (long)bz * (S * 128);
    const __nv_bfloat16* Wl = wwl + (long)bz * (S * 128);
    const __nv_bfloat16* Uh = uh + (long)bz * (S * UK);
    const __nv_bfloat16* Ul = ul + (long)bz * (S * UK);
    const __half* Tb = tTh + (long)bz * (S * DD);
    const float* tb = t + (long)bz * (S * DD);
    float* ab = att + (long)bz * (S * DD);

    const uint32_t sb = (uint32_t)__cvta_generic_to_shared(sm);
    float* part0 = sm + 22528;
    float* part1 = sm + 22592;
    float* mrun  = sm + 22656;
    float* lrun  = sm + 22720;
    float* sscal = sm + 22784;
    __half2* sPh2 = (__half2*)(sm + 20480);

    auto loadWU = [&](const __nv_bfloat16* src, int ld, int row0, int woff) {
        #pragma unroll
        for (int i = tid; i < 768; i += 256) {
            int r = i >> 8, rem = i & 255, row = rem >> 2, c = rem & 3;
            uint32_t dst = sb + (uint32_t)(woff + r * 1024 + row * 16 +
                                           ((c ^ ((row >> 1) & 3)) << 2)) * 4u;
            CP16(dst, (const char*)(src + (long)(row0 + row) * ld + r * 32 + c * 8));
        }
    };
    auto loadT = [&](int kt) {
        #pragma unroll
        for (int i = tid; i < 2048; i += 256) {
            int r = i >> 10, rem = i & 1023, row = rem >> 2, c = rem & 3;
            uint32_t dst = sb + (uint32_t)(12288 + r * 4096 + row * 16 +
                                           ((c ^ ((row >> 1) & 3)) << 2)) * 4u;
            CP16(dst, (const char*)(Tb + (long)row * 1024 + kt * 64 + r * 32 + c * 8));
        }
    };

    if (tid < 64) { mrun[tid] = -1e30f; lrun[tid] = 0.f; }

    float acco[16][4];
    #pragma unroll
    for (int nj = 0; nj < 16; nj++)
        #pragma unroll
        for (int v = 0; v < 4; v++) acco[nj][v] = 0.f;

    loadWU(Wh, 128, m0, 0);
    loadWU(Wl, 128, m0, 3072);
    loadWU(Uh, UK, 0, 6144);
    loadWU(Ul, UK, 0, 9216);
    loadT(0);
    asm volatile("cp.async.commit_group;\n" ::);

    for (int kt = 0; kt <= qt; kt++) {
        asm volatile("cp.async.wait_group 0;\n" ::);
        __syncthreads();

        // ---- score tile 64x64, K=96 bf16-split ----
        float accs[4][4] = {};
        #pragma unroll
        for (int r = 0; r < 3; r++) {
            const float* sWh_ = sm + r * 1024;
            const float* sWl_ = sm + 3072 + r * 1024;
            const float* sUh_ = sm + 6144 + r * 1024;
            const float* sUl_ = sm + 9216 + r * 1024;
            float4 Ah0 = *(const float4*)&sWh_[sw_addr(warp_m + g, cc)];
            float4 Ah1 = *(const float4*)&sWh_[sw_addr(warp_m + g + 8, cc)];
            float4 Al0 = *(const float4*)&sWl_[sw_addr(warp_m + g, cc)];
            float4 Al1 = *(const float4*)&sWl_[sw_addr(warp_m + g + 8, cc)];
            #pragma unroll
            for (int nj = 0; nj < 4; nj++) {
                int nr = warp_n + nj * 8 + g;
                float4 Bh = *(const float4*)&sUh_[sw_addr(nr, cc)];
                float4 Bl = *(const float4*)&sUl_[sw_addr(nr, cc)];
                float* d = accs[nj];
                MMA_BF16(d, UF(Ah0.x), UF(Ah1.x), UF(Ah0.y), UF(Ah1.y), UF(Bh.x), UF(Bh.y));
                MMA_BF16(d, UF(Ah0.x), UF(Ah1.x), UF(Ah0.y), UF(Ah1.y), UF(Bl.x), UF(Bl.y));
                MMA_BF16(d, UF(Al0.x), UF(Al1.x), UF(Al0.y), UF(Al1.y), UF(Bh.x), UF(Bh.y));
                MMA_BF16(d, UF(Ah0.z), UF(Ah1.z), UF(Ah0.w), UF(Ah1.w), UF(Bh.z), UF(Bh.w));
                MMA_BF16(d, UF(Ah0.z), UF(Ah1.z), UF(Ah0.w), UF(Ah1.w), UF(Bl.z), UF(Bl.w));
                MMA_BF16(d, UF(Al0.z), UF(Al1.z), UF(Al0.w), UF(Al1.w), UF(Bh.z), UF(Bh.w));
            }
        }

        // ---- causal mask on diagonal tile ----
        if (kt == qt) {
            #pragma unroll
            for (int nj = 0; nj < 4; nj++)
                #pragma unroll
                for (int v = 0; v < 4; v++) {
                    int cl = warp_n + nj * 8 + 2 * cc + (v & 1);
                    int rl = warp_m + g + ((v & 2) ? 8 : 0);
                    if (cl > rl) accs[nj][v] = -1e30f;
                }
        }

        // ---- row max (quad shfl + cross-warp via smem) ----
        float mx0 = -1e30f, mx1 = -1e30f;
        #pragma unroll
        for (int nj = 0; nj < 4; nj++) {
            mx0 = fmaxf(mx0, fmaxf(accs[nj][0], accs[nj][1]));
            mx1 = fmaxf(mx1, fmaxf(accs[nj][2], accs[nj][3]));
        }
        mx0 = fmaxf(mx0, __shfl_xor_sync(0xffffffffu, mx0, 1));
        mx0 = fmaxf(mx0, __shfl_xor_sync(0xffffffffu, mx0, 2));
        mx1 = fmaxf(mx1, __shfl_xor_sync(0xffffffffu, mx1, 1));
        mx1 = fmaxf(mx1, __shfl_xor_sync(0xffffffffu, mx1, 2));
        if (cc == 0) {
            float* pp = (w >> 2) ? part1 : part0;
            pp[warp_m + g] = mx0;
            pp[warp_m + g + 8] = mx1;
        }
        __syncthreads();

        if (tid < 64) {
            float tm = fmaxf(part0[tid], part1[tid]);
            float mo = mrun[tid];
            float mn = fmaxf(mo, tm);
            sscal[tid] = __expf(mo - mn);
            mrun[tid] = mn;
        }
        // prefetch next U while softmax proceeds (sU free after score MMAs)
        if (kt < qt) {
            loadWU(Uh, UK, (kt + 1) * 64, 6144);
            loadWU(Ul, UK, (kt + 1) * 64, 9216);
            asm volatile("cp.async.commit_group;\n" ::);
        }
        __syncthreads();

        // ---- rescale out, exp, write p (fp16 smem), row sums ----
        float s0 = sscal[warp_m + g], s1 = sscal[warp_m + g + 8];
        #pragma unroll
        for (int nj = 0; nj < 16; nj++) {
            acco[nj][0] *= s0; acco[nj][1] *= s0;
            acco[nj][2] *= s1; acco[nj][3] *= s1;
        }
        float m0r = mrun[warp_m + g], m1r = mrun[warp_m + g + 8];
        float sum0 = 0.f, sum1 = 0.f;
        const int sw0 = ((warp_m + g) >> 1) & 3;
        const int sw1 = ((warp_m + g + 8) >> 1) & 3;
        #pragma unroll
        for (int nj = 0; nj < 4; nj++) {
            float p00 = __expf(accs[nj][0] - m0r);
            float p01 = __expf(accs[nj][1] - m0r);
            float p10 = __expf(accs[nj][2] - m1r);
            float p11 = __expf(accs[nj][3] - m1r);
            sum0 += p00 + p01; sum1 += p10 + p11;
            int colb = warp_n + nj * 8 + 2 * cc;
            int r2 = colb >> 5, kk = colb & 31;
            int ch = (kk >> 1) & 3, pos2 = (kk >> 3) & 3;
            sPh2[r2 * 1024 + (warp_m + g) * 16 + ((ch ^ sw0) << 2) + pos2] =
                __floats2half2_rn(p00, p01);
            sPh2[r2 * 1024 + (warp_m + g + 8) * 16 + ((ch ^ sw1) << 2) + pos2] =
                __floats2half2_rn(p10, p11);
        }
        sum0 += __shfl_xor_sync(0xffffffffu, sum0, 1);
        sum0 += __shfl_xor_sync(0xffffffffu, sum0, 2);
        sum1 += __shfl_xor_sync(0xffffffffu, sum1, 1);
        sum1 += __shfl_xor_sync(0xffffffffu, sum1, 2);
        if (cc == 0) {
            float* pp = (w >> 2) ? part1 : part0;
            pp[warp_m + g] = sum0;
            pp[warp_m + g + 8] = sum1;
        }
        __syncthreads();

        if (tid < 64)
            lrun[tid] = lrun[tid] * sscal[tid] + part0[tid] + part1[tid];

        // ---- PV: acc_o += p(64x64 fp16) . tT-tile^T ----
        #pragma unroll
        for (int r2 = 0; r2 < 2; r2++) {
            const float* sP_ = sm + 20480 + r2 * 1024;
            const float* sT_ = sm + 12288 + r2 * 4096;
            float4 A0 = *(const float4*)&sP_[sw_addr(warp_m + g, cc)];
            float4 A1 = *(const float4*)&sP_[sw_addr(warp_m + g + 8, cc)];
            #pragma unroll
            for (int nj = 0; nj < 16; nj++) {
                int nr = warp_no + nj * 8 + g;
                float4 B = *(const float4*)&sT_[sw_addr(nr, cc)];
                MMA_F16(acco[nj], UF(A0.x), UF(A1.x), UF(A0.y), UF(A1.y), UF(B.x), UF(B.y));
                MMA_F16(acco[nj], UF(A0.z), UF(A1.z), UF(A0.w), UF(A1.w), UF(B.z), UF(B.w));
            }
        }

        if (kt < qt) {
            __syncthreads();               // tT tile free only after all PV done
            loadT(kt + 1);
            asm volatile("cp.async.commit_group;\n" ::);
        }
    }

    __syncthreads();   // lrun final
    const float inv0 = 1.f / lrun[warp_m + g];
    const float inv1 = 1.f / lrun[warp_m + g + 8];
    const int gr0 = m0 + warp_m + g, gr1 = gr0 + 8;
    #pragma unroll
    for (int nj = 0; nj < 16; nj++) {
        int col = warp_no + nj * 8 + 2 * cc;
        float2 r0 = *(const float2*)&tb[(long)gr0 * DD + col];
        float2 r1 = *(const float2*)&tb[(long)gr1 * DD + col];
        *(float2*)&ab[(long)gr0 * DD + col] =
            make_float2(acco[nj][0] * inv0 + r0.x, acco[nj][1] * inv0 + r0.y);
        *(float2*)&ab[(long)gr1 * DD + col] =
            make_float2(acco[nj][2] * inv1 + r1.x, acco[nj][3] * inv1 + r1.y);
    }
}

// ---------------------------------------------------------------------------
// round-8/11 pipelined MMA GEMM (3-stage; single-shot reverted).
// MODE 0: fp16 single-pass BK=64. MODE 1: bf16 2-split BK=32.
// EPI 0: fp32 store 1: relu->fp16 bperm 3: scatter 4:+R->bf16 split 5: bf16 split
// ---------------------------------------------------------------------------
template<int MODE, int EPI>
__global__ __launch_bounds__(256, 2)
void mma_gemm(const void* __restrict__ A, const void* __restrict__ Al_,
              long sAbn, int lda,
              const void* __restrict__ B, const void* __restrict__ Bl_,
              long sBbn, int ldb,
              void* __restrict__ Cv, void* __restrict__ C2v, long sCbn, int ldc,
              const float* __restrict__ R, long sRbn,
              float* __restrict__ Op, int K)
{
    const int bx = blockIdx.x, by = blockIdx.y, bz = blockIdx.z;

    constexpr int SS = 6144;
    extern __shared__ __align__(16) float sh[];

    const int tid = threadIdx.x;
    const int w = tid >> 5, l = tid & 31;
    const int warp_m = (w & 3) * 32, warp_n = (w >> 2) * 32;
    const int g = l >> 2, cc = l & 3;
    const int m0 = by * 128, n0 = bx * 64;

    const char* Abp  = (const char*)A + (long)bz * sAbn * 2;
    const char* Bbp  = (const char*)B + (long)bz * sBbn * 2;
    const char* Ablp = (MODE == 1) ? ((const char*)Al_ + (long)bz * sAbn * 2) : nullptr;
    const char* Bblp = (MODE == 1) ? ((const char*)Bl_ + (long)bz * sBbn * 2) : nullptr;

    const int nk = (MODE == 0) ? (K >> 6) : (K >> 5);

    const int am = tid >> 2, aj = tid & 3;
    const long oA0 = ((long)(m0 + am)      * lda + (long)aj * 8) * 2;
    const long oA1 = ((long)(m0 + am + 64) * lda + (long)aj * 8) * 2;
    const long oB  = ((long)(n0 + am)      * ldb + (long)aj * 8) * 2;
    const int swz  = ((aj ^ ((am >> 1) & 3)) & 3) << 2;
    const int slA0 = am * 16 + swz;
    const int slA1 = (am + 64) * 16 + swz;
    const int slB  = 2048 + am * 16 + swz;
    const uint32_t sbb = (uint32_t)__cvta_generic_to_shared(sh);

    auto issue = [&](int st, int kt) {
        uint32_t s0 = sbb + (uint32_t)(st * SS) * 4u;
        if (MODE == 0) {
            long kb = (long)kt * 128;
            CP16(s0 + slA0 * 4, Abp + oA0 + kb);
            CP16(s0 + slA1 * 4, Abp + oA1 + kb);
            CP16(s0 + slB  * 4, Bbp + oB  + kb);
            CP16(s0 + (slA0 + 3072) * 4, Abp + oA0 + kb + 64);
            CP16(s0 + (slA1 + 3072) * 4, Abp + oA1 + kb + 64);
            CP16(s0 + (slB  + 3072) * 4, Bbp + oB  + kb + 64);
        } else {
            long kb = (long)kt * 64;
            CP16(s0 + slA0 * 4, Abp + oA0 + kb);
            CP16(s0 + slA1 * 4, Abp + oA1 + kb);
            CP16(s0 + slB  * 4, Bbp + oB  + kb);
            CP16(s0 + (slA0 + 3072) * 4, Ablp + oA0 + kb);
            CP16(s0 + (slA1 + 3072) * 4, Ablp + oA1 + kb);
            CP16(s0 + (slB  + 3072) * 4, Bblp + oB  + kb);
        }
        asm volatile("cp.async.commit_group;\n" ::);
    };

    float acc[2][4][4] = {};

    issue(0, 0);
    if (nk > 1) issue(1, 1);
    else        asm volatile("cp.async.commit_group;\n" ::);

    for (int kt = 0; kt < nk; kt++) {
        asm volatile("cp.async.wait_group 1;\n" ::);
        __syncthreads();
        if (kt + 2 < nk) issue((kt + 2) % 3, kt + 2);
        else             asm volatile("cp.async.commit_group;\n" ::);

        const float* s0A = sh + (kt % 3) * SS;
        const float* s0B = s0A + 2048;
        const float* s1A = s0A + 3072;
        const float* s1B = s0A + 5120;

        float4 Ah[2][2], Bh[4], Al[2][2], Bl[4];
        #pragma unroll
        for (int mi = 0; mi < 2; mi++) {
            int mr = warp_m + mi * 16 + g;
            Ah[mi][0] = *(const float4*)&s0A[sw_addr(mr, cc)];
            Ah[mi][1] = *(const float4*)&s0A[sw_addr(mr + 8, cc)];
            Al[mi][0] = *(const float4*)&s1A[sw_addr(mr, cc)];
            Al[mi][1] = *(const float4*)&s1A[sw_addr(mr + 8, cc)];
        }
        #pragma unroll
        for (int nj = 0; nj < 4; nj++) {
            int nr = warp_n + nj * 8 + g;
            Bh[nj] = *(const float4*)&s0B[sw_addr(nr, cc)];
            Bl[nj] = *(const float4*)&s1B[sw_addr(nr, cc)];
        }

        #pragma unroll
        for (int mi = 0; mi < 2; mi++) {
            #pragma unroll
            for (int nj = 0; nj < 4; nj++) {
                float* d = acc[mi][nj];
                if (MODE == 0) {
                    MMA_F16(d, UF(Ah[mi][0].x), UF(Ah[mi][1].x), UF(Ah[mi][0].y), UF(Ah[mi][1].y),
                               UF(Bh[nj].x), UF(Bh[nj].y));
                    MMA_F16(d, UF(Ah[mi][0].z), UF(Ah[mi][1].z), UF(Ah[mi][0].w), UF(Ah[mi][1].w),
                               UF(Bh[nj].z), UF(Bh[nj].w));
                    MMA_F16(d, UF(Al[mi][0].x), UF(Al[mi][1].x), UF(Al[mi][0].y), UF(Al[mi][1].y),
                               UF(Bl[nj].x), UF(Bl[nj].y));
                    MMA_F16(d, UF(Al[mi][0].z), UF(Al[mi][1].z), UF(Al[mi][0].w), UF(Al[mi][1].w),
                               UF(Bl[nj].z), UF(Bl[nj].w));
                } else {
                    MMA_BF16(d, UF(Ah[mi][0].x), UF(Ah[mi][1].x), UF(Ah[mi][0].y), UF(Ah[mi][1].y),
                                UF(Bh[nj].x), UF(Bh[nj].y));
                    MMA_BF16(d, UF(Ah[mi][0].x), UF(Ah[mi][1].x), UF(Ah[mi][0].y), UF(Ah[mi][1].y),
                                UF(Bl[nj].x), UF(Bl[nj].y));
                    MMA_BF16(d, UF(Al[mi][0].x), UF(Al[mi][1].x), UF(Al[mi][0].y), UF(Al[mi][1].y),
                                UF(Bh[nj].x), UF(Bh[nj].y));
                    MMA_BF16(d, UF(Ah[mi][0].z), UF(Ah[mi][1].z), UF(Ah[mi][0].w), UF(Ah[mi][1].w),
                                UF(Bh[nj].z), UF(Bh[nj].w));
                    MMA_BF16(d, UF(Ah[mi][0].z), UF(Ah[mi][1].z), UF(Ah[mi][0].w), UF(Ah[mi][1].w),
                                UF(Bl[nj].z), UF(Bl[nj].w));
                    MMA_BF16(d, UF(Al[mi][0].z), UF(Al[mi][1].z), UF(Al[mi][0].w), UF(Al[mi][1].w),
                                UF(Bh[nj].z), UF(Bh[nj].w));
                }
            }
        }
    }

    if (EPI == 3) {
        const int b = bz >> 3, n = bz & 7;
        #pragma unroll
        for (int mi = 0; mi < 2; mi++) {
            #pragma unroll
            for (int nj = 0; nj < 4; nj++) {
                int row = m0 + warp_m + mi * 16 + g;
                int col = n0 + warp_n + nj * 8 + 2 * cc;
                Op[((long)(b * 64 + col)     * 8 + n) * 1024 + row]     = acc[mi][nj][0];
                Op[((long)(b * 64 + col + 1) * 8 + n) * 1024 + row]     = acc[mi][nj][1];
                Op[((long)(b * 64 + col)     * 8 + n) * 1024 + row + 8] = acc[mi][nj][2];
                Op[((long)(b * 64 + col + 1) * 8 + n) * 1024 + row + 8] = acc[mi][nj][3];
            }
        }
    } else if (EPI == 1) {
        __half* Cb = (__half*)Cv + (long)bz * sCbn;
        #pragma unroll
        for (int mi = 0; mi < 2; mi++) {
            #pragma unroll
            for (int nj = 0; nj < 4; nj++) {
                int row = m0 + warp_m + mi * 16 + g;
                int col = n0 + warp_n + nj * 8 + 2 * cc;
                int p0 = bperm(col);
                *(__half2*)&Cb[(long)row * ldc + p0] =
                    __floats2half2_rn(fmaxf(acc[mi][nj][0], 0.f), fmaxf(acc[mi][nj][1], 0.f));
                *(__half2*)&Cb[(long)(row + 8) * ldc + p0] =
                    __floats2half2_rn(fmaxf(acc[mi][nj][2], 0.f), fmaxf(acc[mi][nj][3], 0.f));
            }
        }
    } else if (EPI == 4 || EPI == 5) {
        __nv_bfloat16* Cb  = (__nv_bfloat16*)Cv  + (long)bz * sCbn;
        __nv_bfloat16* C2b = (__nv_bfloat16*)C2v + (long)bz * sCbn;
        const float* Rb = (EPI == 4) ? (R + (long)bz * sRbn) : nullptr;
        #pragma unroll
        for (int mi = 0; mi < 2; mi++) {
            #pragma unroll
            for (int nj = 0; nj < 4; nj++) {
                int row = m0 + warp_m + mi * 16 + g;
                int col = n0 + warp_n + nj * 8 + 2 * cc;
                int p0 = bperm(col);
                float v[4] = {acc[mi][nj][0], acc[mi][nj][1], acc[mi][nj][2], acc[mi][nj][3]};
                if (EPI == 4) {
                    float2 r0 = *(const float2*)(Rb + (long)row * ldc + col);
                    float2 r1 = *(const float2*)(Rb + (long)(row + 8) * ldc + col);
                    v[0] += r0.x; v[1] += r0.y; v[2] += r1.x; v[3] += r1.y;
                }
                __nv_bfloat16 h[4], lo[4];
                #pragma unroll
                for (int q = 0; q < 4; q++) bf16split(v[q], h[q], lo[q]);
                *(__nv_bfloat162*)&Cb [(long)row * ldc + p0]       = __nv_bfloat162(h[0],  h[1]);
                *(__nv_bfloat162*)&Cb [(long)(row + 8) * ldc + p0] = __nv_bfloat162(h[2],  h[3]);
                *(__nv_bfloat162*)&C2b[(long)row * ldc + p0]       = __nv_bfloat162(lo[0], lo[1]);
                *(__nv_bfloat162*)&C2b[(long)(row + 8) * ldc + p0] = __nv_bfloat162(lo[2], lo[3]);
            }
        }
    } else {
        float* Cb = (float*)Cv + (long)bz * sCbn;
        #pragma unroll
        for (int mi = 0; mi < 2; mi++) {
            #pragma unroll
            for (int nj = 0; nj < 4; nj++) {
                int row = m0 + warp_m + mi * 16 + g;
                int col = n0 + warp_n + nj * 8 + 2 * cc;
                *(float2*)(Cb + (long)row * ldc + col) =
                    make_float2(acc[mi][nj][0], acc[mi][nj][1]);
                *(float2*)(Cb + (long)(row + 8) * ldc + col) =
                    make_float2(acc[mi][nj][2], acc[mi][nj][3]);
            }
        }
    }
}

// ---------------------------------------------------------------------------
__global__ __launch_bounds__(256)
void wprep_k(const float* __restrict__ W_in, const float* __restrict__ W_out,
             const float* __restrict__ W1, const float* __restrict__ W2,
             __nv_bfloat16* __restrict__ wih, __nv_bfloat16* __restrict__ wil,
             __nv_bfloat16* __restrict__ woh, __nv_bfloat16* __restrict__ wol,
             __half* __restrict__ w1h, __half* __restrict__ w2h)
{
    int i = blockIdx.x * 256 + threadIdx.x;
    const int nWi = DD * CD, nWo = CD * DD, nW1 = FD * DD;
    if (i < nWi) {
        int row = i / CD, k = i % CD;
        int o = row * CD + bperm(k);
        bf16split(W_in[i], wih[o], wil[o]);
    } else if (i < nWi + nWo) {
        int j = i - nWi;
        int row = j / DD, k = j % DD;
        int o = row * DD + bperm(k);
        bf16split(W_out[j], woh[o], wol[o]);
    } else if (i < nWi + nWo + nW1) {
        int j = i - nWi - nWo;
        int row = j / DD, k = j % DD;
        w1h[row * DD + bperm(k)] = __float2half_rn(W1[j]);
    } else {
        int j = i - nWi - nWo - nW1;
        if (j < DD * FD) {
            int row = j / FD, k = j % FD;
            w2h[row * FD + bperm(k)] = __float2half_rn(W2[j]);
        }
    }
}

__global__ __launch_bounds__(256)
void gprep_k(const float* __restrict__ W_in, const float* __restrict__ g1,
             const float* __restrict__ b1,
             __nv_bfloat16* __restrict__ gh, __nv_bfloat16* __restrict__ gl)
{
    extern __shared__ float sV[];
    const int tid = threadIdx.x;
    for (int idx = tid; idx < DD * UK; idx += 256) {
        int c = idx / UK, j = idx % UK;
        float gc = g1[c];
        float v = (j < 64) ? gc * W_in[c * CD + j] : ((j == 64) ? -gc : ((j == 65) ? b1[c] : 0.f));
        sV[idx] = v;
    }
    __syncthreads();
    int oidx = blockIdx.x * 256 + tid;
    if (oidx >= 128 * UK) return;
    int n = oidx / UK, k = oidx % UK;
    float val = 0.f;
    if (n < 66 && k < 66) {
        #pragma unroll 4
        for (int c = 0; c < DD; c++)
            val += sV[c * UK + n] * sV[c * UK + k];
    }
    __nv_bfloat16 h, lo;
    bf16split(val, h, lo);
    int o = n * UK + bperm(k);
    gh[o] = h; gl[o] = lo;
}

__global__ __launch_bounds__(256)
void transpose_x_k(const float* __restrict__ x, __nv_bfloat16* __restrict__ xth,
                   __nv_bfloat16* __restrict__ xtl, float* __restrict__ xtf)
{
    __shared__ float tile[32][33];
    int tx = threadIdx.x & 31, ty = threadIdx.x >> 5;
    int bn = blockIdx.z, b = bn >> 3, n = bn & 7;
    int s0 = blockIdx.x * 32, c0 = blockIdx.y * 32;
    const float* src = x + ((long)b * 64 * 8 + n) * 1024;
    #pragma unroll
    for (int i = 0; i < 4; i++)
        tile[ty + 8 * i][tx] = src[(long)(c0 + ty + 8 * i) * 8192 + s0 + tx];
    __syncthreads();
    __nv_bfloat16* dh = xth + (long)bn * (S * CD);
    __nv_bfloat16* dl = xtl + (long)bn * (S * CD);
    float* df = xtf + (long)bn * (S * CD);
    int pc = bperm(c0 + tx);
    #pragma unroll
    for (int i = 0; i < 4; i++) {
        float v = tile[tx][ty + 8 * i];
        long row = (long)(s0 + ty + 8 * i);
        bf16split(v, dh[row * 64 + pc], dl[row * 64 + pc]);
        df[row * 64 + c0 + tx] = v;
    }
}

__global__ __launch_bounds__(256)
void stats_ubuild_k(const float* __restrict__ t, const float* __restrict__ xtf,
                    __nv_bfloat16* __restrict__ uh, __nv_bfloat16* __restrict__ ul)
{
    int warp = (blockIdx.x * blockDim.x + threadIdx.x) >> 5;
    int lane = threadIdx.x & 31;
    const float* x = t + (long)warp * DD;

    float s = 0.f, ss = 0.f;
    #pragma unroll
    for (int i = 0; i < 8; i++) {
        float v = x[lane + 32 * i];
        s += v; ss += v * v;
    }
    #pragma unroll
    for (int o = 16; o; o >>= 1) {
        s  += __shfl_xor_sync(0xffffffffu, s,  o);
        ss += __shfl_xor_sync(0xffffffffu, ss, o);
    }
    float mu = s * (1.f / DD);
    float var = ss * (1.f / DD) - mu * mu;
    float rs = rsqrtf(var + 1e-5f);

    const float* xr = xtf + (long)warp * CD;
    __nv_bfloat16* oh = uh + (long)warp * UK;
    __nv_bfloat16* ol = ul + (long)warp * UK;
    #pragma unroll
    for (int i = 0; i < 3; i++) {
        int j = lane + 32 * i;
        float v;
        if (j < 64)       v = rs * xr[j];
        else if (j == 64) v = rs * mu;
        else if (j == 65) v = 1.f;
        else              v = 0.f;
        __nv_bfloat16 h, lo;
        bf16split(v, h, lo);
        oh[bperm(j)] = h; ol[bperm(j)] = lo;
    }
}

__global__ __launch_bounds__(256)
void transpose_t_k(const float* __restrict__ t, __half* __restrict__ tT)
{
    __shared__ float tile[32][33];
    int tx = threadIdx.x & 31, ty = threadIdx.x >> 5;
    int bn = blockIdx.z;
    int s0 = blockIdx.x * 32, d0 = blockIdx.y * 32;
    const float* src = t + (long)bn * (S * DD);
    #pragma unroll
    for (int i = 0; i < 4; i++)
        tile[ty + 8 * i][tx] = src[(long)(s0 + ty + 8 * i) * 256 + d0 + tx];
    __syncthreads();
    __half* dst = tT + (long)bn * (S * DD);
    int ps = bperm(s0 + tx);
    #pragma unroll
    for (int i = 0; i < 4; i++)
        dst[(long)(d0 + ty + 8 * i) * 1024 + ps] = __float2half_rn(tile[tx][ty + 8 * i]);
}

__global__ __launch_bounds__(256)
void ln_half_k(const float* __restrict__ in, __half* __restrict__ out,
               const float* __restrict__ gam, const float* __restrict__ bet)
{
    int warp = (blockIdx.x * blockDim.x + threadIdx.x) >> 5;
    int lane = threadIdx.x & 31;
    const float* x = in + (long)warp * DD;

    float v[8], s = 0.f, ss = 0.f;
    #pragma unroll
    for (int i = 0; i < 8; i++) {
        v[i] = x[lane + 32 * i];
        s += v[i]; ss += v[i] * v[i];
    }
    #pragma unroll
    for (int o = 16; o; o >>= 1) {
        s  += __shfl_xor_sync(0xffffffffu, s,  o);
        ss += __shfl_xor_sync(0xffffffffu, ss, o);
    }
    float mu = s * (1.f / DD);
    float var = ss * (1.f / DD) - mu * mu;
    float rs = rsqrtf(var + 1e-5f);

    __half* o_ = out + (long)warp * DD;
    #pragma unroll
    for (int i = 0; i < 8; i++) {
        int c = lane + 32 * i;
        o_[bperm(c)] = __float2half_rn((v[i] - mu) * rs * gam[c] + bet[c]);
    }
}

// ---------------------------------------------------------------------------
extern "C" void kernel_launch(void* const* d_in, const int* in_sizes, int n_in,
                              void* d_out, int out_size)
{
    (void)in_sizes; (void)n_in; (void)out_size;
    const float* buffer = (const float*)d_in[0];
    const float* W_in   = (const float*)d_in[1];
    const float* ln1_g  = (const float*)d_in[2];
    const float* ln1_b  = (const float*)d_in[3];
    const float* ln2_g  = (const float*)d_in[4];
    const float* ln2_b  = (const float*)d_in[5];
    const float* W1     = (const float*)d_in[6];
    const float* W2     = (const float*)d_in[7];
    const float* W_out  = (const float*)d_in[8];
    float* out = (float*)d_out;

    __nv_bfloat16 *xth, *xtl, *uh, *ul, *wwh, *wwl, *gh, *gl, *ybh, *ybl;
    __nv_bfloat16 *wih, *wil, *woh, *wol;
    __half *tTh, *hnh, *hfh, *w1h, *w2h;
    float *t, *xtf, *att;
    cudaGetSymbolAddress((void**)&xth, g_xth);
    cudaGetSymbolAddress((void**)&xtl, g_xtl);
    cudaGetSymbolAddress((void**)&uh,  g_uh);
    cudaGetSymbolAddress((void**)&ul,  g_ul);
    cudaGetSymbolAddress((void**)&wwh, g_wwh);
    cudaGetSymbolAddress((void**)&wwl, g_wwl);
    cudaGetSymbolAddress((void**)&gh,  g_gh);
    cudaGetSymbolAddress((void**)&gl,  g_gl);
    cudaGetSymbolAddress((void**)&ybh, g_ybh);
    cudaGetSymbolAddress((void**)&ybl, g_ybl);
    cudaGetSymbolAddress((void**)&wih, g_wih);
    cudaGetSymbolAddress((void**)&wil, g_wil);
    cudaGetSymbolAddress((void**)&woh, g_woh);
    cudaGetSymbolAddress((void**)&wol, g_wol);
    cudaGetSymbolAddress((void**)&tTh, g_tTh);
    cudaGetSymbolAddress((void**)&hnh, g_hnh);
    cudaGetSymbolAddress((void**)&hfh, g_hfh);
    cudaGetSymbolAddress((void**)&w1h, g_w1h);
    cudaGetSymbolAddress((void**)&w2h, g_w2h);
    cudaGetSymbolAddress((void**)&t,   g_t);
    cudaGetSymbolAddress((void**)&xtf, g_xtf);
    cudaGetSymbolAddress((void**)&att, g_att);

    const long sT = (long)S * DD;
    const long sH = (long)S * FD;
    const long sX = (long)S * CD;
    const long sU = (long)S * UK;
    const long sWL = (long)S * 128;

    const int smem_b  = 3 * 6144 * 4;
    const int smem_g  = DD * UK * 4;
    const int smem_fa = 22848 * 4;     // 91392
    cudaFuncSetAttribute(mma_gemm<1, 0>, cudaFuncAttributeMaxDynamicSharedMemorySize, smem_b);
    cudaFuncSetAttribute(mma_gemm<1, 5>, cudaFuncAttributeMaxDynamicSharedMemorySize, smem_b);
    cudaFuncSetAttribute(mma_gemm<0, 1>, cudaFuncAttributeMaxDynamicSharedMemorySize, smem_b);
    cudaFuncSetAttribute(mma_gemm<0, 4>, cudaFuncAttributeMaxDynamicSharedMemorySize, smem_b);
    cudaFuncSetAttribute(mma_gemm<1, 3>, cudaFuncAttributeMaxDynamicSharedMemorySize, smem_b);
    cudaFuncSetAttribute(gprep_k, cudaFuncAttributeMaxDynamicSharedMemorySize, smem_g);
    cudaFuncSetAttribute(fa_k, cudaFuncAttributeMaxDynamicSharedMemorySize, smem_fa);

    {
        const int ntot = DD * CD + CD * DD + FD * DD + DD * FD;
        wprep_k<<<(ntot + 255) / 256, 256>>>(W_in, W_out, W1, W2,
                                             wih, wil, woh, wol, w1h, w2h);
    }
    gprep_k<<<(128 * UK + 255) / 256, 256, smem_g>>>(W_in, ln1_g, ln1_b, gh, gl);

    // 0) transpose x
    transpose_x_k<<<dim3(32, 2, BNT), 256>>>(buffer, xth, xtl, xtf);

    // 1) t = xt . W_in^T
    mma_gemm<1, 0><<<dim3(4, 8, BNT), 256, smem_b>>>(
        xth, xtl, sX, CD,  wih, wil, 0, CD,
        t, nullptr, sT, DD,  nullptr, 0, nullptr, CD);

    // 2) LN1 stats + build U
    stats_ubuild_k<<<(BNT * S) / 8, 256>>>(t, xtf, uh, ul);

    // 3) W = U . G
    mma_gemm<1, 5><<<dim3(2, 8, BNT), 256, smem_b>>>(
        uh, ul, sU, UK,  gh, gl, 0, UK,
        wwh, wwl, sWL, 128,  nullptr, 0, nullptr, UK);

    // 4) transpose t -> tT fp16
    transpose_t_k<<<dim3(32, 8, BNT), 256>>>(t, tTh);

    // 5) FUSED: scores + softmax + P.V + residual  -> att
    fa_k<<<dim3(16, 1, BNT), 256, smem_fa>>>(wwh, wwl, uh, ul, tTh, t, att);

    // 6) hn = LN2(att) -> fp16
    ln_half_k<<<(BNT * S) / 8, 256>>>(att, hnh, ln2_g, ln2_b);

    // 7) hf = relu(hn . W1^T)
    mma_gemm<0, 1><<<dim3(8, 8, BNT), 256, smem_b>>>(
        hnh, nullptr, sT, DD,  w1h, nullptr, 0, DD,
        hfh, nullptr, sH, FD,  nullptr, 0, nullptr, DD);

    // 8) y = hf . W2^T + t -> bf16 hi/lo
    mma_gemm<0, 4><<<dim3(4, 8, BNT), 256, smem_b>>>(
        hfh, nullptr, sH, FD,  w2h, nullptr, 0, FD,
        ybh, ybl, sT, DD,  t, sT, nullptr, FD);

    // 9) out = y . W_out^T (scatter)
    mma_gemm<1, 3><<<dim3(1, 8, BNT), 256, smem_b>>>(
        ybh, ybl, sT, DD,  woh, wol, 0, DD,
        nullptr, nullptr, 0, 0,  nullptr, 0, out, DD);
}

// round 15
// speedup vs baseline: 1.0982x; 1.0549x over previous
#include <cuda_runtime.h>
#include <cuda_bf16.h>
#include <cuda_fp16.h>
#include <cstdint>

#define S    1024
#define CD   64
#define DD   256
#define FD   512
#define BNT  32
#define UK   96

// bf16 split operands (bperm layout)
__device__ __align__(256) __nv_bfloat16 g_xth[BNT * S * CD];
__device__ __align__(256) __nv_bfloat16 g_xtl[BNT * S * CD];
__device__ __align__(256) __nv_bfloat16 g_uh [BNT * S * UK];
__device__ __align__(256) __nv_bfloat16 g_ul [BNT * S * UK];
__device__ __align__(256) __nv_bfloat16 g_wwh[BNT * S * 128];
__device__ __align__(256) __nv_bfloat16 g_wwl[BNT * S * 128];
__device__ __align__(256) __nv_bfloat16 g_gh [128 * UK];
__device__ __align__(256) __nv_bfloat16 g_gl [128 * UK];
__device__ __align__(256) __nv_bfloat16 g_ybh[BNT * S * DD];
__device__ __align__(256) __nv_bfloat16 g_ybl[BNT * S * DD];
__device__ __align__(256) __nv_bfloat16 g_wih[DD * CD];
__device__ __align__(256) __nv_bfloat16 g_wil[DD * CD];
__device__ __align__(256) __nv_bfloat16 g_woh[CD * DD];
__device__ __align__(256) __nv_bfloat16 g_wol[CD * DD];
// fp16 operands (bperm layout)
__device__ __align__(256) __half g_tTh[BNT * S * DD];
__device__ __align__(256) __half g_hnh[BNT * S * DD];
__device__ __align__(256) __half g_hfh[BNT * S * FD];
__device__ __align__(256) __half g_w1h[FD * DD];
__device__ __align__(256) __half g_w2h[DD * FD];
// fp32
__device__ __align__(256) float g_t  [BNT * S * DD];
__device__ __align__(256) float g_xtf[BNT * S * CD];

// ---------------------------------------------------------------------------
__device__ __forceinline__ int bperm(int k) {
    return (k & ~31) | (((k >> 1) & 3) << 3) | (((k >> 3) & 3) << 1) | (k & 1);
}

#define MMA_BF16(d, a0, a1, a2, a3, b0, b1)                                   \
    asm volatile("mma.sync.aligned.m16n8k16.row.col.f32.bf16.bf16.f32 "       \
                 "{%0,%1,%2,%3}, {%4,%5,%6,%7}, {%8,%9}, {%0,%1,%2,%3};\n"    \
                 : "+f"(d[0]), "+f"(d[1]), "+f"(d[2]), "+f"(d[3])             \
                 : "r"(a0), "r"(a1), "r"(a2), "r"(a3), "r"(b0), "r"(b1))

#define MMA_F16(d, a0, a1, a2, a3, b0, b1)                                    \
    asm volatile("mma.sync.aligned.m16n8k16.row.col.f32.f16.f16.f32 "         \
                 "{%0,%1,%2,%3}, {%4,%5,%6,%7}, {%8,%9}, {%0,%1,%2,%3};\n"    \
                 : "+f"(d[0]), "+f"(d[1]), "+f"(d[2]), "+f"(d[3])             \
                 : "r"(a0), "r"(a1), "r"(a2), "r"(a3), "r"(b0), "r"(b1))

#define UF(x) __float_as_uint(x)

#define CP16(dst, src)                                                        \
    asm volatile("cp.async.cg.shared.global [%0], [%1], 16;\n"                \
                 :: "r"(dst), "l"(src))

__device__ __forceinline__ int sw_addr(int m, int q) {
    return m * 16 + (((q ^ ((m >> 1) & 3)) & 3) << 2);
}

__device__ __forceinline__ void bf16split(float v, __nv_bfloat16& h, __nv_bfloat16& l) {
    h = __float2bfloat16_rn(v);
    l = __float2bfloat16_rn(v - __bfloat162float(h));
}

// ---------------------------------------------------------------------------
// Fused flash attention + LN2: scores (W.U^T, K=96 bf16-split) -> online
// softmax -> p.tT (fp16) -> att = p.t/l + t -> LN2 -> hnh (fp16, bperm).
// 1D grid, globally work-sorted (qt=15 CTAs for all bn first).
// smem words: W hi 0 / lo 3072, U hi 6144 / lo 9216, tT 12288 (8192),
//             p 20480 (2048), red 22528..22848
// ---------------------------------------------------------------------------
__global__ __launch_bounds__(256)
void fa_k(const __nv_bfloat16* __restrict__ wwh, const __nv_bfloat16* __restrict__ wwl,
          const __nv_bfloat16* __restrict__ uh,  const __nv_bfloat16* __restrict__ ul,
          const __half* __restrict__ tTh,
          const float* __restrict__ t, __half* __restrict__ hnh,
          const float* __restrict__ gam, const float* __restrict__ bet)
{
    extern __shared__ __align__(16) float sm[];
    const int bid = blockIdx.x;
    const int qt = 15 - (bid >> 5);          // all heaviest tiles first
    const int bz = bid & 31;
    const int m0 = qt * 64;
    const int tid = threadIdx.x;
    const int w = tid >> 5, l = tid & 31;
    const int g = l >> 2, cc = l & 3;
    const int warp_m = (w & 3) * 16;
    const int warp_n = (w >> 2) * 32;
    const int warp_no = (w >> 2) * 128;

    const __nv_bfloat16* Wh = wwh + (long)bz * (S * 128);
    const __nv_bfloat16* Wl = wwl + (long)bz * (S * 128);
    const __nv_bfloat16* Uh = uh + (long)bz * (S * UK);
    const __nv_bfloat16* Ul = ul + (long)bz * (S * UK);
    const __half* Tb = tTh + (long)bz * (S * DD);
    const float* tb = t + (long)bz * (S * DD);
    __half* hb = hnh + (long)bz * (S * DD);

    const uint32_t sb = (uint32_t)__cvta_generic_to_shared(sm);
    float* part0 = sm + 22528;
    float* part1 = sm + 22592;
    float* mrun  = sm + 22656;
    float* lrun  = sm + 22720;
    float* sscal = sm + 22784;
    __half2* sPh2 = (__half2*)(sm + 20480);

    auto loadWU = [&](const __nv_bfloat16* src, int ld, int row0, int woff) {
        #pragma unroll
        for (int i = tid; i < 768; i += 256) {
            int r = i >> 8, rem = i & 255, row = rem >> 2, c = rem & 3;
            uint32_t dst = sb + (uint32_t)(woff + r * 1024 + row * 16 +
                                           ((c ^ ((row >> 1) & 3)) << 2)) * 4u;
            CP16(dst, (const char*)(src + (long)(row0 + row) * ld + r * 32 + c * 8));
        }
    };
    auto loadT = [&](int kt) {
        #pragma unroll
        for (int i = tid; i < 2048; i += 256) {
            int r = i >> 10, rem = i & 1023, row = rem >> 2, c = rem & 3;
            uint32_t dst = sb + (uint32_t)(12288 + r * 4096 + row * 16 +
                                           ((c ^ ((row >> 1) & 3)) << 2)) * 4u;
            CP16(dst, (const char*)(Tb + (long)row * 1024 + kt * 64 + r * 32 + c * 8));
        }
    };

    if (tid < 64) { mrun[tid] = -1e30f; lrun[tid] = 0.f; }

    float acco[16][4];
    #pragma unroll
    for (int nj = 0; nj < 16; nj++)
        #pragma unroll
        for (int v = 0; v < 4; v++) acco[nj][v] = 0.f;

    loadWU(Wh, 128, m0, 0);
    loadWU(Wl, 128, m0, 3072);
    loadWU(Uh, UK, 0, 6144);
    loadWU(Ul, UK, 0, 9216);
    loadT(0);
    asm volatile("cp.async.commit_group;\n" ::);

    for (int kt = 0; kt <= qt; kt++) {
        asm volatile("cp.async.wait_group 0;\n" ::);
        __syncthreads();

        // ---- score tile 64x64, K=96 bf16-split ----
        float accs[4][4] = {};
        #pragma unroll
        for (int r = 0; r < 3; r++) {
            const float* sWh_ = sm + r * 1024;
            const float* sWl_ = sm + 3072 + r * 1024;
            const float* sUh_ = sm + 6144 + r * 1024;
            const float* sUl_ = sm + 9216 + r * 1024;
            float4 Ah0 = *(const float4*)&sWh_[sw_addr(warp_m + g, cc)];
            float4 Ah1 = *(const float4*)&sWh_[sw_addr(warp_m + g + 8, cc)];
            float4 Al0 = *(const float4*)&sWl_[sw_addr(warp_m + g, cc)];
            float4 Al1 = *(const float4*)&sWl_[sw_addr(warp_m + g + 8, cc)];
            #pragma unroll
            for (int nj = 0; nj < 4; nj++) {
                int nr = warp_n + nj * 8 + g;
                float4 Bh = *(const float4*)&sUh_[sw_addr(nr, cc)];
                float4 Bl = *(const float4*)&sUl_[sw_addr(nr, cc)];
                float* d = accs[nj];
                MMA_BF16(d, UF(Ah0.x), UF(Ah1.x), UF(Ah0.y), UF(Ah1.y), UF(Bh.x), UF(Bh.y));
                MMA_BF16(d, UF(Ah0.x), UF(Ah1.x), UF(Ah0.y), UF(Ah1.y), UF(Bl.x), UF(Bl.y));
                MMA_BF16(d, UF(Al0.x), UF(Al1.x), UF(Al0.y), UF(Al1.y), UF(Bh.x), UF(Bh.y));
                MMA_BF16(d, UF(Ah0.z), UF(Ah1.z), UF(Ah0.w), UF(Ah1.w), UF(Bh.z), UF(Bh.w));
                MMA_BF16(d, UF(Ah0.z), UF(Ah1.z), UF(Ah0.w), UF(Ah1.w), UF(Bl.z), UF(Bl.w));
                MMA_BF16(d, UF(Al0.z), UF(Al1.z), UF(Al0.w), UF(Al1.w), UF(Bh.z), UF(Bh.w));
            }
        }

        // ---- causal mask on diagonal tile ----
        if (kt == qt) {
            #pragma unroll
            for (int nj = 0; nj < 4; nj++)
                #pragma unroll
                for (int v = 0; v < 4; v++) {
                    int cl = warp_n + nj * 8 + 2 * cc + (v & 1);
                    int rl = warp_m + g + ((v & 2) ? 8 : 0);
                    if (cl > rl) accs[nj][v] = -1e30f;
                }
        }

        // ---- row max ----
        float mx0 = -1e30f, mx1 = -1e30f;
        #pragma unroll
        for (int nj = 0; nj < 4; nj++) {
            mx0 = fmaxf(mx0, fmaxf(accs[nj][0], accs[nj][1]));
            mx1 = fmaxf(mx1, fmaxf(accs[nj][2], accs[nj][3]));
        }
        mx0 = fmaxf(mx0, __shfl_xor_sync(0xffffffffu, mx0, 1));
        mx0 = fmaxf(mx0, __shfl_xor_sync(0xffffffffu, mx0, 2));
        mx1 = fmaxf(mx1, __shfl_xor_sync(0xffffffffu, mx1, 1));
        mx1 = fmaxf(mx1, __shfl_xor_sync(0xffffffffu, mx1, 2));
        if (cc == 0) {
            float* pp = (w >> 2) ? part1 : part0;
            pp[warp_m + g] = mx0;
            pp[warp_m + g + 8] = mx1;
        }
        __syncthreads();

        if (tid < 64) {
            float tm = fmaxf(part0[tid], part1[tid]);
            float mo = mrun[tid];
            float mn = fmaxf(mo, tm);
            sscal[tid] = __expf(mo - mn);
            mrun[tid] = mn;
        }
        if (kt < qt) {
            loadWU(Uh, UK, (kt + 1) * 64, 6144);
            loadWU(Ul, UK, (kt + 1) * 64, 9216);
            asm volatile("cp.async.commit_group;\n" ::);
        }
        __syncthreads();

        // ---- rescale out, exp, write p (fp16 smem), row sums ----
        float s0 = sscal[warp_m + g], s1 = sscal[warp_m + g + 8];
        #pragma unroll
        for (int nj = 0; nj < 16; nj++) {
            acco[nj][0] *= s0; acco[nj][1] *= s0;
            acco[nj][2] *= s1; acco[nj][3] *= s1;
        }
        float m0r = mrun[warp_m + g], m1r = mrun[warp_m + g + 8];
        float sum0 = 0.f, sum1 = 0.f;
        const int sw0 = ((warp_m + g) >> 1) & 3;
        const int sw1 = ((warp_m + g + 8) >> 1) & 3;
        #pragma unroll
        for (int nj = 0; nj < 4; nj++) {
            float p00 = __expf(accs[nj][0] - m0r);
            float p01 = __expf(accs[nj][1] - m0r);
            float p10 = __expf(accs[nj][2] - m1r);
            float p11 = __expf(accs[nj][3] - m1r);
            sum0 += p00 + p01; sum1 += p10 + p11;
            int colb = warp_n + nj * 8 + 2 * cc;
            int r2 = colb >> 5, kk = colb & 31;
            int ch = (kk >> 1) & 3, pos2 = (kk >> 3) & 3;
            sPh2[r2 * 1024 + (warp_m + g) * 16 + ((ch ^ sw0) << 2) + pos2] =
                __floats2half2_rn(p00, p01);
            sPh2[r2 * 1024 + (warp_m + g + 8) * 16 + ((ch ^ sw1) << 2) + pos2] =
                __floats2half2_rn(p10, p11);
        }
        sum0 += __shfl_xor_sync(0xffffffffu, sum0, 1);
        sum0 += __shfl_xor_sync(0xffffffffu, sum0, 2);
        sum1 += __shfl_xor_sync(0xffffffffu, sum1, 1);
        sum1 += __shfl_xor_sync(0xffffffffu, sum1, 2);
        if (cc == 0) {
            float* pp = (w >> 2) ? part1 : part0;
            pp[warp_m + g] = sum0;
            pp[warp_m + g + 8] = sum1;
        }
        __syncthreads();

        if (tid < 64)
            lrun[tid] = lrun[tid] * sscal[tid] + part0[tid] + part1[tid];

        // ---- PV ----
        #pragma unroll
        for (int r2 = 0; r2 < 2; r2++) {
            const float* sP_ = sm + 20480 + r2 * 1024;
            const float* sT_ = sm + 12288 + r2 * 4096;
            float4 A0 = *(const float4*)&sP_[sw_addr(warp_m + g, cc)];
            float4 A1 = *(const float4*)&sP_[sw_addr(warp_m + g + 8, cc)];
            #pragma unroll
            for (int nj = 0; nj < 16; nj++) {
                int nr = warp_no + nj * 8 + g;
                float4 B = *(const float4*)&sT_[sw_addr(nr, cc)];
                MMA_F16(acco[nj], UF(A0.x), UF(A1.x), UF(A0.y), UF(A1.y), UF(B.x), UF(B.y));
                MMA_F16(acco[nj], UF(A0.z), UF(A1.z), UF(A0.w), UF(A1.w), UF(B.z), UF(B.w));
            }
        }

        if (kt < qt) {
            __syncthreads();
            loadT(kt + 1);
            asm volatile("cp.async.commit_group;\n" ::);
        }
    }

    __syncthreads();   // lrun final
    const float inv0 = 1.f / lrun[warp_m + g];
    const float inv1 = 1.f / lrun[warp_m + g + 8];
    const int gr0 = m0 + warp_m + g, gr1 = gr0 + 8;

    // ---- att rows in registers + LN2 stats ----
    float s0a = 0.f, ss0 = 0.f, s1a = 0.f, ss1 = 0.f;
    #pragma unroll
    for (int nj = 0; nj < 16; nj++) {
        int col = warp_no + nj * 8 + 2 * cc;
        float2 r0 = *(const float2*)&tb[(long)gr0 * DD + col];
        float2 r1 = *(const float2*)&tb[(long)gr1 * DD + col];
        acco[nj][0] = acco[nj][0] * inv0 + r0.x;
        acco[nj][1] = acco[nj][1] * inv0 + r0.y;
        acco[nj][2] = acco[nj][2] * inv1 + r1.x;
        acco[nj][3] = acco[nj][3] * inv1 + r1.y;
        s0a += acco[nj][0] + acco[nj][1];
        ss0 += acco[nj][0] * acco[nj][0] + acco[nj][1] * acco[nj][1];
        s1a += acco[nj][2] + acco[nj][3];
        ss1 += acco[nj][2] * acco[nj][2] + acco[nj][3] * acco[nj][3];
    }
    s0a += __shfl_xor_sync(0xffffffffu, s0a, 1);
    s0a += __shfl_xor_sync(0xffffffffu, s0a, 2);
    ss0 += __shfl_xor_sync(0xffffffffu, ss0, 1);
    ss0 += __shfl_xor_sync(0xffffffffu, ss0, 2);
    s1a += __shfl_xor_sync(0xffffffffu, s1a, 1);
    s1a += __shfl_xor_sync(0xffffffffu, s1a, 2);
    ss1 += __shfl_xor_sync(0xffffffffu, ss1, 1);
    ss1 += __shfl_xor_sync(0xffffffffu, ss1, 2);
    if (cc == 0) {
        float* sumA = (w >> 2) ? part1 : part0;
        float* ssqA = (w >> 2) ? sscal : mrun;
        sumA[warp_m + g] = s0a;  sumA[warp_m + g + 8] = s1a;
        ssqA[warp_m + g] = ss0;  ssqA[warp_m + g + 8] = ss1;
    }
    __syncthreads();
    if (tid < 64) {
        float mu = (part0[tid] + part1[tid]) * (1.f / DD);
        float var = (mrun[tid] + sscal[tid]) * (1.f / DD) - mu * mu;
        part0[tid] = mu;
        part1[tid] = rsqrtf(var + 1e-5f);
    }
    __syncthreads();
    const float mu0 = part0[warp_m + g], rs0 = part1[warp_m + g];
    const float mu1 = part0[warp_m + g + 8], rs1 = part1[warp_m + g + 8];
    #pragma unroll
    for (int nj = 0; nj < 16; nj++) {
        int col = warp_no + nj * 8 + 2 * cc;
        float g0 = gam[col], g1v = gam[col + 1];
        float b0 = bet[col], b1v = bet[col + 1];
        int pc = bperm(col);
        *(__half2*)&hb[(long)gr0 * DD + pc] = __floats2half2_rn(
            (acco[nj][0] - mu0) * rs0 * g0 + b0,
            (acco[nj][1] - mu0) * rs0 * g1v + b1v);
        *(__half2*)&hb[(long)gr1 * DD + pc] = __floats2half2_rn(
            (acco[nj][2] - mu1) * rs1 * g0 + b0,
            (acco[nj][3] - mu1) * rs1 * g1v + b1v);
    }
}

// ---------------------------------------------------------------------------
// round-8/11 pipelined MMA GEMM.
// MODE 0: fp16 single-pass BK=64. MODE 1: bf16 2-split BK=32.
// EPI 0: fp32 store 1: relu->fp16 bperm 3: scatter 4:+R->bf16 split 5: bf16 split
// ---------------------------------------------------------------------------
template<int MODE, int EPI>
__global__ __launch_bounds__(256, 2)
void mma_gemm(const void* __restrict__ A, const void* __restrict__ Al_,
              long sAbn, int lda,
              const void* __restrict__ B, const void* __restrict__ Bl_,
              long sBbn, int ldb,
              void* __restrict__ Cv, void* __restrict__ C2v, long sCbn, int ldc,
              const float* __restrict__ R, long sRbn,
              float* __restrict__ Op, int K)
{
    const int bx = blockIdx.x, by = blockIdx.y, bz = blockIdx.z;

    constexpr int SS = 6144;
    extern __shared__ __align__(16) float sh[];

    const int tid = threadIdx.x;
    const int w = tid >> 5, l = tid & 31;
    const int warp_m = (w & 3) * 32, warp_n = (w >> 2) * 32;
    const int g = l >> 2, cc = l & 3;
    const int m0 = by * 128, n0 = bx * 64;

    const char* Abp  = (const char*)A + (long)bz * sAbn * 2;
    const char* Bbp  = (const char*)B + (long)bz * sBbn * 2;
    const char* Ablp = (MODE == 1) ? ((const char*)Al_ + (long)bz * sAbn * 2) : nullptr;
    const char* Bblp = (MODE == 1) ? ((const char*)Bl_ + (long)bz * sBbn * 2) : nullptr;

    const int nk = (MODE == 0) ? (K >> 6) : (K >> 5);

    const int am = tid >> 2, aj = tid & 3;
    const long oA0 = ((long)(m0 + am)      * lda + (long)aj * 8) * 2;
    const long oA1 = ((long)(m0 + am + 64) * lda + (long)aj * 8) * 2;
    const long oB  = ((long)(n0 + am)      * ldb + (long)aj * 8) * 2;
    const int swz  = ((aj ^ ((am >> 1) & 3)) & 3) << 2;
    const int slA0 = am * 16 + swz;
    const int slA1 = (am + 64) * 16 + swz;
    const int slB  = 2048 + am * 16 + swz;
    const uint32_t sbb = (uint32_t)__cvta_generic_to_shared(sh);

    auto issue = [&](int st, int kt) {
        uint32_t s0 = sbb + (uint32_t)(st * SS) * 4u;
        if (MODE == 0) {
            long kb = (long)kt * 128;
            CP16(s0 + slA0 * 4, Abp + oA0 + kb);
            CP16(s0 + slA1 * 4, Abp + oA1 + kb);
            CP16(s0 + slB  * 4, Bbp + oB  + kb);
            CP16(s0 + (slA0 + 3072) * 4, Abp + oA0 + kb + 64);
            CP16(s0 + (slA1 + 3072) * 4, Abp + oA1 + kb + 64);
            CP16(s0 + (slB  + 3072) * 4, Bbp + oB  + kb + 64);
        } else {
            long kb = (long)kt * 64;
            CP16(s0 + slA0 * 4, Abp + oA0 + kb);
            CP16(s0 + slA1 * 4, Abp + oA1 + kb);
            CP16(s0 + slB  * 4, Bbp + oB  + kb);
            CP16(s0 + (slA0 + 3072) * 4, Ablp + oA0 + kb);
            CP16(s0 + (slA1 + 3072) * 4, Ablp + oA1 + kb);
            CP16(s0 + (slB  + 3072) * 4, Bblp + oB  + kb);
        }
        asm volatile("cp.async.commit_group;\n" ::);
    };

    float acc[2][4][4] = {};

    issue(0, 0);
    if (nk > 1) issue(1, 1);
    else        asm volatile("cp.async.commit_group;\n" ::);

    for (int kt = 0; kt < nk; kt++) {
        asm volatile("cp.async.wait_group 1;\n" ::);
        __syncthreads();
        if (kt + 2 < nk) issue((kt + 2) % 3, kt + 2);
        else             asm volatile("cp.async.commit_group;\n" ::);

        const float* s0A = sh + (kt % 3) * SS;
        const float* s0B = s0A + 2048;
        const float* s1A = s0A + 3072;
        const float* s1B = s0A + 5120;

        float4 Ah[2][2], Bh[4], Al[2][2], Bl[4];
        #pragma unroll
        for (int mi = 0; mi < 2; mi++) {
            int mr = warp_m + mi * 16 + g;
            Ah[mi][0] = *(const float4*)&s0A[sw_addr(mr, cc)];
            Ah[mi][1] = *(const float4*)&s0A[sw_addr(mr + 8, cc)];
            Al[mi][0] = *(const float4*)&s1A[sw_addr(mr, cc)];
            Al[mi][1] = *(const float4*)&s1A[sw_addr(mr + 8, cc)];
        }
        #pragma unroll
        for (int nj = 0; nj < 4; nj++) {
            int nr = warp_n + nj * 8 + g;
            Bh[nj] = *(const float4*)&s0B[sw_addr(nr, cc)];
            Bl[nj] = *(const float4*)&s1B[sw_addr(nr, cc)];
        }

        #pragma unroll
        for (int mi = 0; mi < 2; mi++) {
            #pragma unroll
            for (int nj = 0; nj < 4; nj++) {
                float* d = acc[mi][nj];
                if (MODE == 0) {
                    MMA_F16(d, UF(Ah[mi][0].x), UF(Ah[mi][1].x), UF(Ah[mi][0].y), UF(Ah[mi][1].y),
                               UF(Bh[nj].x), UF(Bh[nj].y));
                    MMA_F16(d, UF(Ah[mi][0].z), UF(Ah[mi][1].z), UF(Ah[mi][0].w), UF(Ah[mi][1].w),
                               UF(Bh[nj].z), UF(Bh[nj].w));
                    MMA_F16(d, UF(Al[mi][0].x), UF(Al[mi][1].x), UF(Al[mi][0].y), UF(Al[mi][1].y),
                               UF(Bl[nj].x), UF(Bl[nj].y));
                    MMA_F16(d, UF(Al[mi][0].z), UF(Al[mi][1].z), UF(Al[mi][0].w), UF(Al[mi][1].w),
                               UF(Bl[nj].z), UF(Bl[nj].w));
                } else {
                    MMA_BF16(d, UF(Ah[mi][0].x), UF(Ah[mi][1].x), UF(Ah[mi][0].y), UF(Ah[mi][1].y),
                                UF(Bh[nj].x), UF(Bh[nj].y));
                    MMA_BF16(d, UF(Ah[mi][0].x), UF(Ah[mi][1].x), UF(Ah[mi][0].y), UF(Ah[mi][1].y),
                                UF(Bl[nj].x), UF(Bl[nj].y));
                    MMA_BF16(d, UF(Al[mi][0].x), UF(Al[mi][1].x), UF(Al[mi][0].y), UF(Al[mi][1].y),
                                UF(Bh[nj].x), UF(Bh[nj].y));
                    MMA_BF16(d, UF(Ah[mi][0].z), UF(Ah[mi][1].z), UF(Ah[mi][0].w), UF(Ah[mi][1].w),
                                UF(Bh[nj].z), UF(Bh[nj].w));
                    MMA_BF16(d, UF(Ah[mi][0].z), UF(Ah[mi][1].z), UF(Ah[mi][0].w), UF(Ah[mi][1].w),
                                UF(Bl[nj].z), UF(Bl[nj].w));
                    MMA_BF16(d, UF(Al[mi][0].z), UF(Al[mi][1].z), UF(Al[mi][0].w), UF(Al[mi][1].w),
                                UF(Bh[nj].z), UF(Bh[nj].w));
                }
            }
        }
    }

    if (EPI == 3) {
        const int b = bz >> 3, n = bz & 7;
        #pragma unroll
        for (int mi = 0; mi < 2; mi++) {
            #pragma unroll
            for (int nj = 0; nj < 4; nj++) {
                int row = m0 + warp_m + mi * 16 + g;
                int col = n0 + warp_n + nj * 8 + 2 * cc;
                Op[((long)(b * 64 + col)     * 8 + n) * 1024 + row]     = acc[mi][nj][0];
                Op[((long)(b * 64 + col + 1) * 8 + n) * 1024 + row]     = acc[mi][nj][1];
                Op[((long)(b * 64 + col)     * 8 + n) * 1024 + row + 8] = acc[mi][nj][2];
                Op[((long)(b * 64 + col + 1) * 8 + n) * 1024 + row + 8] = acc[mi][nj][3];
            }
        }
    } else if (EPI == 1) {
        __half* Cb = (__half*)Cv + (long)bz * sCbn;
        #pragma unroll
        for (int mi = 0; mi < 2; mi++) {
            #pragma unroll
            for (int nj = 0; nj < 4; nj++) {
                int row = m0 + warp_m + mi * 16 + g;
                int col = n0 + warp_n + nj * 8 + 2 * cc;
                int p0 = bperm(col);
                *(__half2*)&Cb[(long)row * ldc + p0] =
                    __floats2half2_rn(fmaxf(acc[mi][nj][0], 0.f), fmaxf(acc[mi][nj][1], 0.f));
                *(__half2*)&Cb[(long)(row + 8) * ldc + p0] =
                    __floats2half2_rn(fmaxf(acc[mi][nj][2], 0.f), fmaxf(acc[mi][nj][3], 0.f));
            }
        }
    } else if (EPI == 4 || EPI == 5) {
        __nv_bfloat16* Cb  = (__nv_bfloat16*)Cv  + (long)bz * sCbn;
        __nv_bfloat16* C2b = (__nv_bfloat16*)C2v + (long)bz * sCbn;
        const float* Rb = (EPI == 4) ? (R + (long)bz * sRbn) : nullptr;
        #pragma unroll
        for (int mi = 0; mi < 2; mi++) {
            #pragma unroll
            for (int nj = 0; nj < 4; nj++) {
                int row = m0 + warp_m + mi * 16 + g;
                int col = n0 + warp_n + nj * 8 + 2 * cc;
                int p0 = bperm(col);
                float v[4] = {acc[mi][nj][0], acc[mi][nj][1], acc[mi][nj][2], acc[mi][nj][3]};
                if (EPI == 4) {
                    float2 r0 = *(const float2*)(Rb + (long)row * ldc + col);
                    float2 r1 = *(const float2*)(Rb + (long)(row + 8) * ldc + col);
                    v[0] += r0.x; v[1] += r0.y; v[2] += r1.x; v[3] += r1.y;
                }
                __nv_bfloat16 h[4], lo[4];
                #pragma unroll
                for (int q = 0; q < 4; q++) bf16split(v[q], h[q], lo[q]);
                *(__nv_bfloat162*)&Cb [(long)row * ldc + p0]       = __nv_bfloat162(h[0],  h[1]);
                *(__nv_bfloat162*)&Cb [(long)(row + 8) * ldc + p0] = __nv_bfloat162(h[2],  h[3]);
                *(__nv_bfloat162*)&C2b[(long)row * ldc + p0]       = __nv_bfloat162(lo[0], lo[1]);
                *(__nv_bfloat162*)&C2b[(long)(row + 8) * ldc + p0] = __nv_bfloat162(lo[2], lo[3]);
            }
        }
    } else {
        float* Cb = (float*)Cv + (long)bz * sCbn;
        #pragma unroll
        for (int mi = 0; mi < 2; mi++) {
            #pragma unroll
            for (int nj = 0; nj < 4; nj++) {
                int row = m0 + warp_m + mi * 16 + g;
                int col = n0 + warp_n + nj * 8 + 2 * cc;
                *(float2*)(Cb + (long)row * ldc + col) =
                    make_float2(acc[mi][nj][0], acc[mi][nj][1]);
                *(float2*)(Cb + (long)(row + 8) * ldc + col) =
                    make_float2(acc[mi][nj][2], acc[mi][nj][3]);
            }
        }
    }
}

// ---------------------------------------------------------------------------
__global__ __launch_bounds__(256)
void wprep_k(const float* __restrict__ W_in, const float* __restrict__ W_out,
             const float* __restrict__ W1, const float* __restrict__ W2,
             __nv_bfloat16* __restrict__ wih, __nv_bfloat16* __restrict__ wil,
             __nv_bfloat16* __restrict__ woh, __nv_bfloat16* __restrict__ wol,
             __half* __restrict__ w1h, __half* __restrict__ w2h)
{
    int i = blockIdx.x * 256 + threadIdx.x;
    const int nWi = DD * CD, nWo = CD * DD, nW1 = FD * DD;
    if (i < nWi) {
        int row = i / CD, k = i % CD;
        int o = row * CD + bperm(k);
        bf16split(W_in[i], wih[o], wil[o]);
    } else if (i < nWi + nWo) {
        int j = i - nWi;
        int row = j / DD, k = j % DD;
        int o = row * DD + bperm(k);
        bf16split(W_out[j], woh[o], wol[o]);
    } else if (i < nWi + nWo + nW1) {
        int j = i - nWi - nWo;
        int row = j / DD, k = j % DD;
        w1h[row * DD + bperm(k)] = __float2half_rn(W1[j]);
    } else {
        int j = i - nWi - nWo - nW1;
        if (j < DD * FD) {
            int row = j / FD, k = j % FD;
            w2h[row * FD + bperm(k)] = __float2half_rn(W2[j]);
        }
    }
}

__global__ __launch_bounds__(256)
void gprep_k(const float* __restrict__ W_in, const float* __restrict__ g1,
             const float* __restrict__ b1,
             __nv_bfloat16* __restrict__ gh, __nv_bfloat16* __restrict__ gl)
{
    extern __shared__ float sV[];
    const int tid = threadIdx.x;
    for (int idx = tid; idx < DD * UK; idx += 256) {
        int c = idx / UK, j = idx % UK;
        float gc = g1[c];
        float v = (j < 64) ? gc * W_in[c * CD + j] : ((j == 64) ? -gc : ((j == 65) ? b1[c] : 0.f));
        sV[idx] = v;
    }
    __syncthreads();
    int oidx = blockIdx.x * 256 + tid;
    if (oidx >= 128 * UK) return;
    int n = oidx / UK, k = oidx % UK;
    float val = 0.f;
    if (n < 66 && k < 66) {
        #pragma unroll 4
        for (int c = 0; c < DD; c++)
            val += sV[c * UK + n] * sV[c * UK + k];
    }
    __nv_bfloat16 h, lo;
    bf16split(val, h, lo);
    int o = n * UK + bperm(k);
    gh[o] = h; gl[o] = lo;
}

__global__ __launch_bounds__(256)
void transpose_x_k(const float* __restrict__ x, __nv_bfloat16* __restrict__ xth,
                   __nv_bfloat16* __restrict__ xtl, float* __restrict__ xtf)
{
    __shared__ float tile[32][33];
    int tx = threadIdx.x & 31, ty = threadIdx.x >> 5;
    int bn = blockIdx.z, b = bn >> 3, n = bn & 7;
    int s0 = blockIdx.x * 32, c0 = blockIdx.y * 32;
    const float* src = x + ((long)b * 64 * 8 + n) * 1024;
    #pragma unroll
    for (int i = 0; i < 4; i++)
        tile[ty + 8 * i][tx] = src[(long)(c0 + ty + 8 * i) * 8192 + s0 + tx];
    __syncthreads();
    __nv_bfloat16* dh = xth + (long)bn * (S * CD);
    __nv_bfloat16* dl = xtl + (long)bn * (S * CD);
    float* df = xtf + (long)bn * (S * CD);
    int pc = bperm(c0 + tx);
    #pragma unroll
    for (int i = 0; i < 4; i++) {
        float v = tile[tx][ty + 8 * i];
        long row = (long)(s0 + ty + 8 * i);
        bf16split(v, dh[row * 64 + pc], dl[row * 64 + pc]);
        df[row * 64 + c0 + tx] = v;
    }
}

__global__ __launch_bounds__(256)
void stats_ubuild_k(const float* __restrict__ t, const float* __restrict__ xtf,
                    __nv_bfloat16* __restrict__ uh, __nv_bfloat16* __restrict__ ul)
{
    int warp = (blockIdx.x * blockDim.x + threadIdx.x) >> 5;
    int lane = threadIdx.x & 31;
    const float* x = t + (long)warp * DD;

    float s = 0.f, ss = 0.f;
    #pragma unroll
    for (int i = 0; i < 8; i++) {
        float v = x[lane + 32 * i];
        s += v; ss += v * v;
    }
    #pragma unroll
    for (int o = 16; o; o >>= 1) {
        s  += __shfl_xor_sync(0xffffffffu, s,  o);
        ss += __shfl_xor_sync(0xffffffffu, ss, o);
    }
    float mu = s * (1.f / DD);
    float var = ss * (1.f / DD) - mu * mu;
    float rs = rsqrtf(var + 1e-5f);

    const float* xr = xtf + (long)warp * CD;
    __nv_bfloat16* oh = uh + (long)warp * UK;
    __nv_bfloat16* ol = ul + (long)warp * UK;
    #pragma unroll
    for (int i = 0; i < 3; i++) {
        int j = lane + 32 * i;
        float v;
        if (j < 64)       v = rs * xr[j];
        else if (j == 64) v = rs * mu;
        else if (j == 65) v = 1.f;
        else              v = 0.f;
        __nv_bfloat16 h, lo;
        bf16split(v, h, lo);
        oh[bperm(j)] = h; ol[bperm(j)] = lo;
    }
}

__global__ __launch_bounds__(256)
void transpose_t_k(const float* __restrict__ t, __half* __restrict__ tT)
{
    __shared__ float tile[32][33];
    int tx = threadIdx.x & 31, ty = threadIdx.x >> 5;
    int bn = blockIdx.z;
    int s0 = blockIdx.x * 32, d0 = blockIdx.y * 32;
    const float* src = t + (long)bn * (S * DD);
    #pragma unroll
    for (int i = 0; i < 4; i++)
        tile[ty + 8 * i][tx] = src[(long)(s0 + ty + 8 * i) * 256 + d0 + tx];
    __syncthreads();
    __half* dst = tT + (long)bn * (S * DD);
    int ps = bperm(s0 + tx);
    #pragma unroll
    for (int i = 0; i < 4; i++)
        dst[(long)(d0 + ty + 8 * i) * 1024 + ps] = __float2half_rn(tile[tx][ty + 8 * i]);
}

// ---------------------------------------------------------------------------
extern "C" void kernel_launch(void* const* d_in, const int* in_sizes, int n_in,
                              void* d_out, int out_size)
{
    (void)in_sizes; (void)n_in; (void)out_size;
    const float* buffer = (const float*)d_in[0];
    const float* W_in   = (const float*)d_in[1];
    const float* ln1_g  = (const float*)d_in[2];
    const float* ln1_b  = (const float*)d_in[3];
    const float* ln2_g  = (const float*)d_in[4];
    const float* ln2_b  = (const float*)d_in[5];
    const float* W1     = (const float*)d_in[6];
    const float* W2     = (const float*)d_in[7];
    const float* W_out  = (const float*)d_in[8];
    float* out = (float*)d_out;

    __nv_bfloat16 *xth, *xtl, *uh, *ul, *wwh, *wwl, *gh, *gl, *ybh, *ybl;
    __nv_bfloat16 *wih, *wil, *woh, *wol;
    __half *tTh, *hnh, *hfh, *w1h, *w2h;
    float *t, *xtf;
    cudaGetSymbolAddress((void**)&xth, g_xth);
    cudaGetSymbolAddress((void**)&xtl, g_xtl);
    cudaGetSymbolAddress((void**)&uh,  g_uh);
    cudaGetSymbolAddress((void**)&ul,  g_ul);
    cudaGetSymbolAddress((void**)&wwh, g_wwh);
    cudaGetSymbolAddress((void**)&wwl, g_wwl);
    cudaGetSymbolAddress((void**)&gh,  g_gh);
    cudaGetSymbolAddress((void**)&gl,  g_gl);
    cudaGetSymbolAddress((void**)&ybh, g_ybh);
    cudaGetSymbolAddress((void**)&ybl, g_ybl);
    cudaGetSymbolAddress((void**)&wih, g_wih);
    cudaGetSymbolAddress((void**)&wil, g_wil);
    cudaGetSymbolAddress((void**)&woh, g_woh);
    cudaGetSymbolAddress((void**)&wol, g_wol);
    cudaGetSymbolAddress((void**)&tTh, g_tTh);
    cudaGetSymbolAddress((void**)&hnh, g_hnh);
    cudaGetSymbolAddress((void**)&hfh, g_hfh);
    cudaGetSymbolAddress((void**)&w1h, g_w1h);
    cudaGetSymbolAddress((void**)&w2h, g_w2h);
    cudaGetSymbolAddress((void**)&t,   g_t);
    cudaGetSymbolAddress((void**)&xtf, g_xtf);

    const long sT = (long)S * DD;
    const long sH = (long)S * FD;
    const long sX = (long)S * CD;
    const long sU = (long)S * UK;
    const long sWL = (long)S * 128;

    const int smem_b  = 3 * 6144 * 4;
    const int smem_g  = DD * UK * 4;
    const int smem_fa = 22848 * 4;
    cudaFuncSetAttribute(mma_gemm<1, 0>, cudaFuncAttributeMaxDynamicSharedMemorySize, smem_b);
    cudaFuncSetAttribute(mma_gemm<1, 5>, cudaFuncAttributeMaxDynamicSharedMemorySize, smem_b);
    cudaFuncSetAttribute(mma_gemm<0, 1>, cudaFuncAttributeMaxDynamicSharedMemorySize, smem_b);
    cudaFuncSetAttribute(mma_gemm<0, 4>, cudaFuncAttributeMaxDynamicSharedMemorySize, smem_b);
    cudaFuncSetAttribute(mma_gemm<1, 3>, cudaFuncAttributeMaxDynamicSharedMemorySize, smem_b);
    cudaFuncSetAttribute(gprep_k, cudaFuncAttributeMaxDynamicSharedMemorySize, smem_g);
    cudaFuncSetAttribute(fa_k, cudaFuncAttributeMaxDynamicSharedMemorySize, smem_fa);

    {
        const int ntot = DD * CD + CD * DD + FD * DD + DD * FD;
        wprep_k<<<(ntot + 255) / 256, 256>>>(W_in, W_out, W1, W2,
                                             wih, wil, woh, wol, w1h, w2h);
    }
    gprep_k<<<(128 * UK + 255) / 256, 256, smem_g>>>(W_in, ln1_g, ln1_b, gh, gl);

    // 0) transpose x
    transpose_x_k<<<dim3(32, 2, BNT), 256>>>(buffer, xth, xtl, xtf);

    // 1) t = xt . W_in^T
    mma_gemm<1, 0><<<dim3(4, 8, BNT), 256, smem_b>>>(
        xth, xtl, sX, CD,  wih, wil, 0, CD,
        t, nullptr, sT, DD,  nullptr, 0, nullptr, CD);

    // 2) LN1 stats + build U
    stats_ubuild_k<<<(BNT * S) / 8, 256>>>(t, xtf, uh, ul);

    // 3) W = U . G
    mma_gemm<1, 5><<<dim3(2, 8, BNT), 256, smem_b>>>(
        uh, ul, sU, UK,  gh, gl, 0, UK,
        wwh, wwl, sWL, 128,  nullptr, 0, nullptr, UK);

    // 4) transpose t -> tT fp16
    transpose_t_k<<<dim3(32, 8, BNT), 256>>>(t, tTh);

    // 5) FUSED: scores + softmax + P.V + residual + LN2 -> hnh (fp16)
    fa_k<<<512, 256, smem_fa>>>(wwh, wwl, uh, ul, tTh, t, hnh, ln2_g, ln2_b);

    // 6) hf = relu(hn . W1^T)
    mma_gemm<0, 1><<<dim3(8, 8, BNT), 256, smem_b>>>(
        hnh, nullptr, sT, DD,  w1h, nullptr, 0, DD,
        hfh, nullptr, sH, FD,  nullptr, 0, nullptr, DD);

    // 7) y = hf . W2^T + t -> bf16 hi/lo
    mma_gemm<0, 4><<<dim3(4, 8, BNT), 256, smem_b>>>(
        hfh, nullptr, sH, FD,  w2h, nullptr, 0, FD,
        ybh, ybl, sT, DD,  t, sT, nullptr, FD);

    // 8) out = y . W_out^T (scatter)
    mma_gemm<1, 3><<<dim3(1, 8, BNT), 256, smem_b>>>(
        ybh, ybl, sT, DD,  woh, wol, 0, DD,
        nullptr, nullptr, 0, 0,  nullptr, 0, out, DD);
}